// round 7
// baseline (speedup 1.0000x reference)
#include <cuda_runtime.h>
#include <cstdint>

#define TT 4096
#define CC 768
#define HH 12
#define DH 64

// ---------------- device scratch (allocation-free rule) ----------------
__device__ float g_xt [TT * CC];        // x, tf32-rounded
__device__ float g_q  [HH * TT * DH];   // [h][t][d], pre-scaled by 0.125*log2e, tf32
__device__ float g_k  [HH * TT * DH];   // [h][t][d], tf32
__device__ float g_vt [HH * DH * TT];   // [h][d][t], tf32
__device__ float g_att[TT * CC];        // concat heads, tf32
__device__ float g_wt [3 * CC * CC];    // qkv weights [j][k], tf32
__device__ float g_wot[CC * CC];        // wo as [n][k], tf32

// ---------------- helpers ----------------
static __device__ __forceinline__ uint32_t smem_u32(const void* p) {
    uint32_t a;
    asm("{ .reg .u64 t; cvta.to.shared.u64 t, %1; cvt.u32.u64 %0, t; }" : "=r"(a) : "l"(p));
    return a;
}
static __device__ __forceinline__ uint32_t tf32r(float f) {
    uint32_t u; asm("cvt.rna.tf32.f32 %0, %1;" : "=r"(u) : "f"(f)); return u;
}
static __device__ __forceinline__ float ex2(float x) {
    float y; asm("ex2.approx.f32 %0, %1;" : "=f"(y) : "f"(x)); return y;
}
static __device__ __forceinline__ void mma8(float* d, const uint32_t* a, const uint32_t* b) {
    asm volatile(
        "mma.sync.aligned.m16n8k8.row.col.f32.tf32.tf32.f32 "
        "{%0,%1,%2,%3}, {%4,%5,%6,%7}, {%8,%9}, {%0,%1,%2,%3};"
        : "+f"(d[0]), "+f"(d[1]), "+f"(d[2]), "+f"(d[3])
        : "r"(a[0]), "r"(a[1]), "r"(a[2]), "r"(a[3]), "r"(b[0]), "r"(b[1]));
}
static __device__ __forceinline__ uint4 cvt4(float4 v) {
    uint4 t; t.x = tf32r(v.x); t.y = tf32r(v.y); t.z = tf32r(v.z); t.w = tf32r(v.w);
    return t;
}
static __device__ __forceinline__ void cpa(uint32_t dst, const void* src) {
    asm volatile("cp.async.cg.shared.global [%0], [%1], 16;" :: "r"(dst), "l"(src));
}
static __device__ __forceinline__ void cp_commit() {
    asm volatile("cp.async.commit_group;" ::: "memory");
}
template <int N> static __device__ __forceinline__ void cp_wait() {
    asm volatile("cp.async.wait_group %0;" :: "n"(N) : "memory");
}

// ---------------- merged preprocessing: cvt_x + 3x tr_head + tr_wo ----------------
// grid: [0,3072) cvt_x; [3072,3216) wq; [3216,3360) wk; [3360,3504) wv; [3504,3648) wo
__global__ __launch_bounds__(256) void prep(
    const float* __restrict__ x,
    const float* __restrict__ wq, const float* __restrict__ wk,
    const float* __restrict__ wv, const float* __restrict__ wo)
{
    const int b = blockIdx.x;
    if (b < 3072) {
        int i = b * 256 + threadIdx.x;
        float4 v = ((const float4*)x)[i];
        ((uint4*)g_xt)[i] = cvt4(v);
        return;
    }
    __shared__ float t[64][65];
    if (b < 3504) {
        const int bb = b - 3072;
        const int sel = bb / 144, r = bb % 144;
        const int k0 = (r % 12) * 64, h = r / 12;
        const float* src = (sel == 0) ? wq : (sel == 1) ? wk : wv;
        const float* s = src + (size_t)h * CC * DH;
        #pragma unroll
        for (int i = 0; i < 16; i++) {
            int e = threadIdx.x + i * 256; int kr = e >> 6, d = e & 63;
            t[kr][d] = s[(size_t)(k0 + kr) * DH + d];
        }
        __syncthreads();
        const int j0 = sel * CC;
        #pragma unroll
        for (int i = 0; i < 16; i++) {
            int e = threadIdx.x + i * 256; int d = e >> 6, kr = e & 63;
            g_wt[(size_t)(j0 + h * DH + d) * CC + k0 + kr] = __uint_as_float(tf32r(t[kr][d]));
        }
    } else {
        const int r = b - 3504;
        const int c0 = (r % 12) * 64, n0 = (r / 12) * 64;
        #pragma unroll
        for (int i = 0; i < 16; i++) {
            int e = threadIdx.x + i * 256; int cr = e >> 6, n = e & 63;
            t[cr][n] = wo[(size_t)(c0 + cr) * CC + n0 + n];
        }
        __syncthreads();
        #pragma unroll
        for (int i = 0; i < 16; i++) {
            int e = threadIdx.x + i * 256; int n = e >> 6, cr = e & 63;
            g_wot[(size_t)(n0 + n) * CC + c0 + cr] = __uint_as_float(tf32r(t[cr][n]));
        }
    }
}

// ---------------- GEMM (tf32 mma.sync + cp.async): MODE 0 = qkv, MODE 1 = out --------
#define GBUF 4608              // 128*36 u32 per matrix
#define GBUFSZ 9216            // per buffer (A+B)

template <int MODE>
__global__ __launch_bounds__(256, 2) void gemm_k(
    const float* __restrict__ Am, const float* __restrict__ Bm,
    const float* __restrict__ x0, const float* __restrict__ x1,
    const float* __restrict__ x2, float* __restrict__ outp)
{
    extern __shared__ uint32_t sm[];
    const uint32_t usm = smem_u32(sm);
    const int tid = threadIdx.x;
    const int warp = tid >> 5, lane = tid & 31;
    const int g = lane >> 2, q = lane & 3;
    const int warp_m = warp & 3, warp_n = warp >> 2;
    const int m0 = blockIdx.x * 128, n0 = blockIdx.y * 128;

    auto ldgsts = [&](int k0, int buf) {
        const uint32_t uA = usm + buf * GBUFSZ * 4;
        const uint32_t uB = uA + GBUF * 4;
        #pragma unroll
        for (int i = 0; i < 4; i++) {
            int idx = tid + i * 256; int r = idx >> 3, cc = idx & 7;
            cpa(uA + (r * 36 + cc * 4) * 4, Am + (size_t)(m0 + r) * CC + k0 + cc * 4);
            cpa(uB + (r * 36 + cc * 4) * 4, Bm + (size_t)(n0 + r) * CC + k0 + cc * 4);
        }
        cp_commit();
    };

    float Cf[2][8][4];
    #pragma unroll
    for (int tm = 0; tm < 2; tm++)
        #pragma unroll
        for (int tn = 0; tn < 8; tn++)
            #pragma unroll
            for (int k = 0; k < 4; k++) Cf[tm][tn][k] = 0.f;

    ldgsts(0, 0);

    for (int c = 0; c < 24; c++) {
        cp_wait<0>();
        __syncthreads();
        if (c < 23) ldgsts((c + 1) * 32, (c + 1) & 1);
        const uint32_t* sA = sm + (c & 1) * GBUFSZ;
        const uint32_t* sB = sA + GBUF;
        #pragma unroll
        for (int ks = 0; ks < 4; ks++) {
            uint32_t a[2][4];
            #pragma unroll
            for (int tm = 0; tm < 2; tm++) {
                int row = warp_m * 32 + tm * 16 + g;
                a[tm][0] = sA[row * 36 + ks * 8 + q];
                a[tm][1] = sA[(row + 8) * 36 + ks * 8 + q];
                a[tm][2] = sA[row * 36 + ks * 8 + q + 4];
                a[tm][3] = sA[(row + 8) * 36 + ks * 8 + q + 4];
            }
            #pragma unroll
            for (int tn = 0; tn < 8; tn++) {
                uint32_t b[2];
                int col = warp_n * 64 + tn * 8 + g;
                b[0] = sB[col * 36 + ks * 8 + q];
                b[1] = sB[col * 36 + ks * 8 + q + 4];
                mma8(Cf[0][tn], a[0], b);
                mma8(Cf[1][tn], a[1], b);
            }
        }
        __syncthreads();
    }

    const int jb = n0 + warp_n * 64;
    if (MODE == 0) {
        const float c1 = 0.18033688011112042f;   // 0.125 * log2(e)
        const int sel = jb / CC, rem = jb % CC, h = rem >> 6;
        const float* bias = (sel == 0) ? x0 : (sel == 1) ? x1 : x2;
        #pragma unroll
        for (int tm = 0; tm < 2; tm++) {
            const int t0 = m0 + warp_m * 32 + tm * 16 + g;
            #pragma unroll
            for (int tn = 0; tn < 8; tn++) {
                const int d = tn * 8 + 2 * q;
                const float b0 = bias[h * DH + d], b1 = bias[h * DH + d + 1];
                float v00 = Cf[tm][tn][0] + b0, v01 = Cf[tm][tn][1] + b1;
                float v10 = Cf[tm][tn][2] + b0, v11 = Cf[tm][tn][3] + b1;
                if (sel == 0) {
                    float* dst = g_q + (size_t)h * TT * DH;
                    uint2 p0 = { tf32r(v00 * c1), tf32r(v01 * c1) };
                    uint2 p1 = { tf32r(v10 * c1), tf32r(v11 * c1) };
                    *(uint2*)(dst + (size_t)t0 * DH + d) = p0;
                    *(uint2*)(dst + (size_t)(t0 + 8) * DH + d) = p1;
                } else if (sel == 1) {
                    float* dst = g_k + (size_t)h * TT * DH;
                    uint2 p0 = { tf32r(v00), tf32r(v01) };
                    uint2 p1 = { tf32r(v10), tf32r(v11) };
                    *(uint2*)(dst + (size_t)t0 * DH + d) = p0;
                    *(uint2*)(dst + (size_t)(t0 + 8) * DH + d) = p1;
                } else {
                    float* dst = g_vt + (size_t)h * DH * TT;
                    dst[(size_t)d * TT + t0]           = __uint_as_float(tf32r(v00));
                    dst[(size_t)(d + 1) * TT + t0]     = __uint_as_float(tf32r(v01));
                    dst[(size_t)d * TT + t0 + 8]       = __uint_as_float(tf32r(v10));
                    dst[(size_t)(d + 1) * TT + t0 + 8] = __uint_as_float(tf32r(v11));
                }
            }
        }
    } else {
        const float* bo = x0;
        #pragma unroll
        for (int tm = 0; tm < 2; tm++) {
            const int t0 = m0 + warp_m * 32 + tm * 16 + g;
            #pragma unroll
            for (int tn = 0; tn < 8; tn++) {
                const int j = jb + tn * 8 + 2 * q;
                const float b0 = bo[j], b1 = bo[j + 1];
                float2 v0 = { Cf[tm][tn][0] + b0, Cf[tm][tn][1] + b1 };
                float2 v1 = { Cf[tm][tn][2] + b0, Cf[tm][tn][3] + b1 };
                *(float2*)(outp + (size_t)t0 * CC + j) = v0;
                *(float2*)(outp + (size_t)(t0 + 8) * CC + j) = v1;
            }
        }
    }
}

// ---------------- flash attention (tf32 mma.sync, fat-warp + mma row-sums) ----------
// 128 threads = 4 warps; Q block 128 rows; warp = 32 rows (2 m16 tiles) x 64 keys.
// smem (u32): Ps[128][68] @0, K[2][64][68] @8704, V[2][72][68] @17408.
//   V rows 0..63 = V^T data (d-major); row 64 = 1.0 (sum column); rows 65..71 = 0.
// Row-sums l come out of the PV mma as an extra n-chunk -> no per-iter sum shuffles.
#define ABUF 4352   // 64*68 (K buffer)
#define VBUF 4896   // 72*68 (V buffer incl. ones row)

__global__ __launch_bounds__(128, 2) void attn()
{
    extern __shared__ uint32_t sm[];
    uint32_t* Ps = sm;
    const uint32_t uPs = smem_u32(sm);

    const int tid = threadIdx.x;
    const int warp = tid >> 5, lane = tid & 31;
    const int g = lane >> 2, q = lane & 3;
    const int qb = 31 - blockIdx.x;    // largest work first
    const int h  = blockIdx.y;
    const int rb = warp * 32;          // warp row base within the 128-row block

    const float* Qg = g_q  + (size_t)h * TT * DH + (size_t)qb * 128 * DH;
    const float* Kg = g_k  + (size_t)h * TT * DH;
    const float* Vg = g_vt + (size_t)h * DH * TT;

    const int nj = 2 * qb + 2;

    auto load_kv = [&](int j, int buf) {
        const uint32_t uK = uPs + (8704 + buf * ABUF) * 4;
        const uint32_t uV = uPs + (17408 + buf * VBUF) * 4;
        #pragma unroll
        for (int i = 0; i < 8; i++) {
            int idx = tid + i * 128; int r = idx >> 4, cc = idx & 15;
            cpa(uK + (r * 68 + cc * 4) * 4, Kg + (size_t)(j * 64 + r) * DH + cc * 4);
            cpa(uV + (r * 68 + cc * 4) * 4, Vg + (size_t)r * TT + j * 64 + cc * 4);
        }
        cp_commit();
    };

    // init V sum rows (row 64 = 1.0, rows 65..71 = 0) for both buffers
    for (int i = tid; i < 2 * 8 * 68; i += 128) {
        int b = i / (8 * 68), rr = (i / 68) % 8, cc = i % 68;
        sm[17408 + b * VBUF + (64 + rr) * 68 + cc] = (rr == 0) ? 0x3F800000u : 0u;
    }

    // stage Q into Ps, prefetch KV block 0
    #pragma unroll
    for (int i = 0; i < 16; i++) {
        int idx = tid + i * 128; int r = idx >> 4, cc = idx & 15;
        cpa(uPs + (r * 68 + cc * 4) * 4, Qg + (size_t)r * DH + cc * 4);
    }
    cp_commit();
    load_kv(0, 0);
    cp_wait<0>();
    __syncthreads();

    // Q fragments -> registers
    uint32_t A[2][8][4];
    #pragma unroll
    for (int tm = 0; tm < 2; tm++) {
        const int base = rb + tm * 16;
        #pragma unroll
        for (int ks = 0; ks < 8; ks++) {
            A[tm][ks][0] = Ps[(base + g) * 68 + ks * 8 + q];
            A[tm][ks][1] = Ps[(base + 8 + g) * 68 + ks * 8 + q];
            A[tm][ks][2] = Ps[(base + g) * 68 + ks * 8 + q + 4];
            A[tm][ks][3] = Ps[(base + 8 + g) * 68 + ks * 8 + q + 4];
        }
    }
    __syncthreads();   // Ps now reusable as P

    float O[2][8][4];
    float L[2][4];     // sum-column fragments: c0 = l(row g) at q==0, c2 = l(row g+8)
    #pragma unroll
    for (int tm = 0; tm < 2; tm++) {
        #pragma unroll
        for (int tn = 0; tn < 8; tn++)
            #pragma unroll
            for (int k = 0; k < 4; k++) O[tm][tn][k] = 0.f;
        #pragma unroll
        for (int k = 0; k < 4; k++) L[tm][k] = 0.f;
    }
    float mv[4];
    #pragma unroll
    for (int i = 0; i < 4; i++) mv[i] = -1e30f;

    const int r0 = qb * 128 + rb + g;

    for (int j = 0; j < nj; j++) {
        if (j) { cp_wait<0>(); __syncthreads(); }
        if (j + 1 < nj) load_kv(j + 1, (j + 1) & 1);

        // entire 32-row x 64-key tile above the diagonal? (warps 0,1 on last block)
        if (j * 64 > qb * 128 + rb + 31) continue;

        const uint32_t* Ks = sm + 8704 + (j & 1) * ABUF;
        const uint32_t* Vs = sm + 17408 + (j & 1) * VBUF;

        // S = Q @ K^T (log2 domain; Q pre-scaled)
        float S[2][8][4];
        #pragma unroll
        for (int tm = 0; tm < 2; tm++)
            #pragma unroll
            for (int tn = 0; tn < 8; tn++)
                #pragma unroll
                for (int k = 0; k < 4; k++) S[tm][tn][k] = 0.f;
        #pragma unroll
        for (int ks = 0; ks < 8; ks++) {
            #pragma unroll
            for (int tn = 0; tn < 8; tn++) {
                uint32_t b[2];
                b[0] = Ks[(tn * 8 + g) * 68 + ks * 8 + q];
                b[1] = Ks[(tn * 8 + g) * 68 + ks * 8 + q + 4];
                mma8(S[0][tn], A[0][ks], b);
                mma8(S[1][tn], A[1][ks], b);
            }
        }

        // causal mask (diagonal key-blocks only)
        if (j >= 2 * qb) {
            const int kb = j * 64;
            #pragma unroll
            for (int tn = 0; tn < 8; tn++) {
                const int col = kb + tn * 8 + 2 * q;
                #pragma unroll
                for (int tm = 0; tm < 2; tm++) {
                    const int ra = r0 + tm * 16, rb2 = ra + 8;
                    if (col > ra)      S[tm][tn][0] = -1e30f;
                    if (col + 1 > ra)  S[tm][tn][1] = -1e30f;
                    if (col > rb2)     S[tm][tn][2] = -1e30f;
                    if (col + 1 > rb2) S[tm][tn][3] = -1e30f;
                }
            }
        }

        // online softmax: max update only (sums come from the mma ones-column)
        float tmax[4] = { -1e30f, -1e30f, -1e30f, -1e30f };
        #pragma unroll
        for (int tm = 0; tm < 2; tm++)
            #pragma unroll
            for (int tn = 0; tn < 8; tn++) {
                tmax[tm * 2]     = fmaxf(tmax[tm * 2],     fmaxf(S[tm][tn][0], S[tm][tn][1]));
                tmax[tm * 2 + 1] = fmaxf(tmax[tm * 2 + 1], fmaxf(S[tm][tn][2], S[tm][tn][3]));
            }
        float al[4];
        #pragma unroll
        for (int i = 0; i < 4; i++) {
            tmax[i] = fmaxf(tmax[i], __shfl_xor_sync(0xffffffffu, tmax[i], 1));
            tmax[i] = fmaxf(tmax[i], __shfl_xor_sync(0xffffffffu, tmax[i], 2));
            const float mn = fmaxf(mv[i], tmax[i]);
            al[i] = ex2(mv[i] - mn);
            mv[i] = mn;
        }
        #pragma unroll
        for (int tm = 0; tm < 2; tm++)
            #pragma unroll
            for (int tn = 0; tn < 8; tn++) {
                S[tm][tn][0] = ex2(S[tm][tn][0] - mv[tm * 2]);
                S[tm][tn][1] = ex2(S[tm][tn][1] - mv[tm * 2]);
                S[tm][tn][2] = ex2(S[tm][tn][2] - mv[tm * 2 + 1]);
                S[tm][tn][3] = ex2(S[tm][tn][3] - mv[tm * 2 + 1]);
            }

        // P -> smem (warp-private rows)
        #pragma unroll
        for (int tm = 0; tm < 2; tm++) {
            const int base = rb + tm * 16;
            #pragma unroll
            for (int tn = 0; tn < 8; tn++) {
                uint2 p0 = { tf32r(S[tm][tn][0]), tf32r(S[tm][tn][1]) };
                uint2 p1 = { tf32r(S[tm][tn][2]), tf32r(S[tm][tn][3]) };
                *(uint2*)(Ps + (base + g) * 68 + tn * 8 + 2 * q) = p0;
                *(uint2*)(Ps + (base + 8 + g) * 68 + tn * 8 + 2 * q) = p1;
            }
        }
        __syncwarp();

        // rescale O and L (skip when no row max changed anywhere in the warp)
        if (__any_sync(0xffffffffu,
                       (al[0] != 1.f) | (al[1] != 1.f) | (al[2] != 1.f) | (al[3] != 1.f))) {
            #pragma unroll
            for (int tm = 0; tm < 2; tm++) {
                #pragma unroll
                for (int tn = 0; tn < 8; tn++) {
                    O[tm][tn][0] *= al[tm * 2];     O[tm][tn][1] *= al[tm * 2];
                    O[tm][tn][2] *= al[tm * 2 + 1]; O[tm][tn][3] *= al[tm * 2 + 1];
                }
                L[tm][0] *= al[tm * 2];
                L[tm][2] *= al[tm * 2 + 1];
            }
        }

        // accumulate P @ [V | ones]
        #pragma unroll
        for (int ks = 0; ks < 8; ks++) {
            uint32_t a[2][4];
            #pragma unroll
            for (int tm = 0; tm < 2; tm++) {
                const int base = rb + tm * 16;
                a[tm][0] = Ps[(base + g) * 68 + ks * 8 + q];
                a[tm][1] = Ps[(base + 8 + g) * 68 + ks * 8 + q];
                a[tm][2] = Ps[(base + g) * 68 + ks * 8 + q + 4];
                a[tm][3] = Ps[(base + 8 + g) * 68 + ks * 8 + q + 4];
            }
            #pragma unroll
            for (int tn = 0; tn < 8; tn++) {
                uint32_t b[2];
                b[0] = Vs[(tn * 8 + g) * 68 + ks * 8 + q];
                b[1] = Vs[(tn * 8 + g) * 68 + ks * 8 + q + 4];
                mma8(O[0][tn], a[0], b);
                mma8(O[1][tn], a[1], b);
            }
            {   // sum column chunk (rows 64..71 of Vs; row 64 = ones)
                uint32_t b[2];
                b[0] = Vs[(64 + g) * 68 + ks * 8 + q];
                b[1] = Vs[(64 + g) * 68 + ks * 8 + q + 4];
                mma8(L[0], a[0], b);
                mma8(L[1], a[1], b);
            }
        }
        __syncwarp();
    }

    // epilogue: broadcast l (held in q==0 lanes), normalize, tf32-round
    #pragma unroll
    for (int tm = 0; tm < 2; tm++) {
        const int ra = r0 + tm * 16;
        const float l0 = __shfl_sync(0xffffffffu, L[tm][0], lane & 28);
        const float l1 = __shfl_sync(0xffffffffu, L[tm][2], lane & 28);
        const float i0 = 1.f / l0, i1 = 1.f / l1;
        #pragma unroll
        for (int tn = 0; tn < 8; tn++) {
            const int d = tn * 8 + 2 * q;
            uint2 v0 = { tf32r(O[tm][tn][0] * i0), tf32r(O[tm][tn][1] * i0) };
            uint2 v1 = { tf32r(O[tm][tn][2] * i1), tf32r(O[tm][tn][3] * i1) };
            *(uint2*)(g_att + (size_t)ra * CC + h * DH + d) = v0;
            *(uint2*)(g_att + (size_t)(ra + 8) * CC + h * DH + d) = v1;
        }
    }
}

// ---------------- launcher ----------------
extern "C" void kernel_launch(void* const* d_in, const int* in_sizes, int n_in,
                              void* d_out, int out_size)
{
    const float* x  = (const float*)d_in[0];
    const float* wq = (const float*)d_in[1];
    const float* bq = (const float*)d_in[2];
    const float* wk = (const float*)d_in[3];
    const float* bk = (const float*)d_in[4];
    const float* wv = (const float*)d_in[5];
    const float* bv = (const float*)d_in[6];
    const float* wo = (const float*)d_in[7];
    const float* bo = (const float*)d_in[8];

    const int GSM = 2 * GBUFSZ * 4;            // 73728 B
    const int ASM = (8704 + 2 * ABUF + 2 * VBUF) * 4;  // 108800 B
    cudaFuncSetAttribute(gemm_k<0>, cudaFuncAttributeMaxDynamicSharedMemorySize, GSM);
    cudaFuncSetAttribute(gemm_k<1>, cudaFuncAttributeMaxDynamicSharedMemorySize, GSM);
    cudaFuncSetAttribute(attn,      cudaFuncAttributeMaxDynamicSharedMemorySize, ASM);

    float* xt_dev;  cudaGetSymbolAddress((void**)&xt_dev,  g_xt);
    float* wt_dev;  cudaGetSymbolAddress((void**)&wt_dev,  g_wt);
    float* wot_dev; cudaGetSymbolAddress((void**)&wot_dev, g_wot);
    float* att_dev; cudaGetSymbolAddress((void**)&att_dev, g_att);

    prep<<<3648, 256>>>(x, wq, wk, wv, wo);
    gemm_k<0><<<dim3(32, 18), 256, GSM>>>(xt_dev, wt_dev, bq, bk, bv, nullptr);
    attn<<<dim3(32, 12), 128, ASM>>>();
    gemm_k<1><<<dim3(32, 6), 256, GSM>>>(att_dev, wot_dev, bo, nullptr, nullptr, (float*)d_out);
}

// round 8
// speedup vs baseline: 1.0695x; 1.0695x over previous
#include <cuda_runtime.h>
#include <cstdint>

#define TT 4096
#define CC 768
#define HH 12
#define DH 64

// ---------------- device scratch (allocation-free rule) ----------------
__device__ float g_xt [TT * CC];        // x, tf32-rounded
__device__ float g_q  [HH * TT * DH];   // [h][t][d], pre-scaled by 0.125*log2e, tf32
__device__ float g_k  [HH * TT * DH];   // [h][t][d], tf32
__device__ float g_vt [HH * DH * TT];   // [h][d][t], tf32
__device__ float g_att[TT * CC];        // concat heads, tf32
__device__ float g_wt [3 * CC * CC];    // qkv weights [j][k], tf32
__device__ float g_wot[CC * CC];        // wo as [n][k], tf32

// ---------------- helpers ----------------
static __device__ __forceinline__ uint32_t smem_u32(const void* p) {
    uint32_t a;
    asm("{ .reg .u64 t; cvta.to.shared.u64 t, %1; cvt.u32.u64 %0, t; }" : "=r"(a) : "l"(p));
    return a;
}
static __device__ __forceinline__ uint32_t tf32r(float f) {
    uint32_t u; asm("cvt.rna.tf32.f32 %0, %1;" : "=r"(u) : "f"(f)); return u;
}
static __device__ __forceinline__ float ex2(float x) {
    float y; asm("ex2.approx.f32 %0, %1;" : "=f"(y) : "f"(x)); return y;
}
static __device__ __forceinline__ void mma8(float* d, const uint32_t* a, const uint32_t* b) {
    asm volatile(
        "mma.sync.aligned.m16n8k8.row.col.f32.tf32.tf32.f32 "
        "{%0,%1,%2,%3}, {%4,%5,%6,%7}, {%8,%9}, {%0,%1,%2,%3};"
        : "+f"(d[0]), "+f"(d[1]), "+f"(d[2]), "+f"(d[3])
        : "r"(a[0]), "r"(a[1]), "r"(a[2]), "r"(a[3]), "r"(b[0]), "r"(b[1]));
}
static __device__ __forceinline__ uint4 cvt4(float4 v) {
    uint4 t; t.x = tf32r(v.x); t.y = tf32r(v.y); t.z = tf32r(v.z); t.w = tf32r(v.w);
    return t;
}
static __device__ __forceinline__ void cpa(uint32_t dst, const void* src) {
    asm volatile("cp.async.cg.shared.global [%0], [%1], 16;" :: "r"(dst), "l"(src));
}
static __device__ __forceinline__ void cp_commit() {
    asm volatile("cp.async.commit_group;" ::: "memory");
}
template <int N> static __device__ __forceinline__ void cp_wait() {
    asm volatile("cp.async.wait_group %0;" :: "n"(N) : "memory");
}

// ---------------- merged preprocessing: cvt_x + 3x tr_head + tr_wo ----------------
__global__ __launch_bounds__(256) void prep(
    const float* __restrict__ x,
    const float* __restrict__ wq, const float* __restrict__ wk,
    const float* __restrict__ wv, const float* __restrict__ wo)
{
    const int b = blockIdx.x;
    if (b < 3072) {
        int i = b * 256 + threadIdx.x;
        float4 v = ((const float4*)x)[i];
        ((uint4*)g_xt)[i] = cvt4(v);
        return;
    }
    __shared__ float t[64][65];
    if (b < 3504) {
        const int bb = b - 3072;
        const int sel = bb / 144, r = bb % 144;
        const int k0 = (r % 12) * 64, h = r / 12;
        const float* src = (sel == 0) ? wq : (sel == 1) ? wk : wv;
        const float* s = src + (size_t)h * CC * DH;
        #pragma unroll
        for (int i = 0; i < 16; i++) {
            int e = threadIdx.x + i * 256; int kr = e >> 6, d = e & 63;
            t[kr][d] = s[(size_t)(k0 + kr) * DH + d];
        }
        __syncthreads();
        const int j0 = sel * CC;
        #pragma unroll
        for (int i = 0; i < 16; i++) {
            int e = threadIdx.x + i * 256; int d = e >> 6, kr = e & 63;
            g_wt[(size_t)(j0 + h * DH + d) * CC + k0 + kr] = __uint_as_float(tf32r(t[kr][d]));
        }
    } else {
        const int r = b - 3504;
        const int c0 = (r % 12) * 64, n0 = (r / 12) * 64;
        #pragma unroll
        for (int i = 0; i < 16; i++) {
            int e = threadIdx.x + i * 256; int cr = e >> 6, n = e & 63;
            t[cr][n] = wo[(size_t)(c0 + cr) * CC + n0 + n];
        }
        __syncthreads();
        #pragma unroll
        for (int i = 0; i < 16; i++) {
            int e = threadIdx.x + i * 256; int n = e >> 6, cr = e & 63;
            g_wot[(size_t)(n0 + n) * CC + c0 + cr] = __uint_as_float(tf32r(t[cr][n]));
        }
    }
}

// ---------------- GEMM (tf32 mma.sync, 3-stage cp.async): MODE 0 = qkv, 1 = out -----
// C tile 128 x 128, BK = 32, 8 warps (4 m x 2 n). 3 smem stages, 1 barrier/iter.
#define GBUF 4608              // 128*36 u32 per matrix
#define GBUFSZ 9216            // per stage (A+B)

template <int MODE>
__global__ __launch_bounds__(256, 2) void gemm_k(
    const float* __restrict__ Am, const float* __restrict__ Bm,
    const float* __restrict__ x0, const float* __restrict__ x1,
    const float* __restrict__ x2, float* __restrict__ outp)
{
    extern __shared__ uint32_t sm[];
    const uint32_t usm = smem_u32(sm);
    const int tid = threadIdx.x;
    const int warp = tid >> 5, lane = tid & 31;
    const int g = lane >> 2, q = lane & 3;
    const int warp_m = warp & 3, warp_n = warp >> 2;
    const int m0 = blockIdx.x * 128, n0 = blockIdx.y * 128;

    auto ldgsts = [&](int k0, int buf) {
        const uint32_t uA = usm + buf * GBUFSZ * 4;
        const uint32_t uB = uA + GBUF * 4;
        #pragma unroll
        for (int i = 0; i < 4; i++) {
            int idx = tid + i * 256; int r = idx >> 3, cc = idx & 7;
            cpa(uA + (r * 36 + cc * 4) * 4, Am + (size_t)(m0 + r) * CC + k0 + cc * 4);
            cpa(uB + (r * 36 + cc * 4) * 4, Bm + (size_t)(n0 + r) * CC + k0 + cc * 4);
        }
        cp_commit();
    };

    float Cf[2][8][4];
    #pragma unroll
    for (int tm = 0; tm < 2; tm++)
        #pragma unroll
        for (int tn = 0; tn < 8; tn++)
            #pragma unroll
            for (int k = 0; k < 4; k++) Cf[tm][tn][k] = 0.f;

    ldgsts(0, 0);
    ldgsts(32, 1);

    int buf = 0;
    for (int c = 0; c < 24; c++) {
        cp_wait<1>();           // chunk c has landed (c+1 may still be in flight)
        __syncthreads();
        if (c < 22) ldgsts((c + 2) * 32, (c + 2) % 3);
        const uint32_t* sA = sm + buf * GBUFSZ;
        const uint32_t* sB = sA + GBUF;
        #pragma unroll
        for (int ks = 0; ks < 4; ks++) {
            uint32_t a[2][4];
            #pragma unroll
            for (int tm = 0; tm < 2; tm++) {
                int row = warp_m * 32 + tm * 16 + g;
                a[tm][0] = sA[row * 36 + ks * 8 + q];
                a[tm][1] = sA[(row + 8) * 36 + ks * 8 + q];
                a[tm][2] = sA[row * 36 + ks * 8 + q + 4];
                a[tm][3] = sA[(row + 8) * 36 + ks * 8 + q + 4];
            }
            #pragma unroll
            for (int tn = 0; tn < 8; tn++) {
                uint32_t b[2];
                int col = warp_n * 64 + tn * 8 + g;
                b[0] = sB[col * 36 + ks * 8 + q];
                b[1] = sB[col * 36 + ks * 8 + q + 4];
                mma8(Cf[0][tn], a[0], b);
                mma8(Cf[1][tn], a[1], b);
            }
        }
        buf = (buf + 1) % 3;
    }

    const int jb = n0 + warp_n * 64;
    if (MODE == 0) {
        const float c1 = 0.18033688011112042f;   // 0.125 * log2(e)
        const int sel = jb / CC, rem = jb % CC, h = rem >> 6;
        const float* bias = (sel == 0) ? x0 : (sel == 1) ? x1 : x2;
        #pragma unroll
        for (int tm = 0; tm < 2; tm++) {
            const int t0 = m0 + warp_m * 32 + tm * 16 + g;
            #pragma unroll
            for (int tn = 0; tn < 8; tn++) {
                const int d = tn * 8 + 2 * q;
                const float b0 = bias[h * DH + d], b1 = bias[h * DH + d + 1];
                float v00 = Cf[tm][tn][0] + b0, v01 = Cf[tm][tn][1] + b1;
                float v10 = Cf[tm][tn][2] + b0, v11 = Cf[tm][tn][3] + b1;
                if (sel == 0) {
                    float* dst = g_q + (size_t)h * TT * DH;
                    uint2 p0 = { tf32r(v00 * c1), tf32r(v01 * c1) };
                    uint2 p1 = { tf32r(v10 * c1), tf32r(v11 * c1) };
                    *(uint2*)(dst + (size_t)t0 * DH + d) = p0;
                    *(uint2*)(dst + (size_t)(t0 + 8) * DH + d) = p1;
                } else if (sel == 1) {
                    float* dst = g_k + (size_t)h * TT * DH;
                    uint2 p0 = { tf32r(v00), tf32r(v01) };
                    uint2 p1 = { tf32r(v10), tf32r(v11) };
                    *(uint2*)(dst + (size_t)t0 * DH + d) = p0;
                    *(uint2*)(dst + (size_t)(t0 + 8) * DH + d) = p1;
                } else {
                    float* dst = g_vt + (size_t)h * DH * TT;
                    dst[(size_t)d * TT + t0]           = __uint_as_float(tf32r(v00));
                    dst[(size_t)(d + 1) * TT + t0]     = __uint_as_float(tf32r(v01));
                    dst[(size_t)d * TT + t0 + 8]       = __uint_as_float(tf32r(v10));
                    dst[(size_t)(d + 1) * TT + t0 + 8] = __uint_as_float(tf32r(v11));
                }
            }
        }
    } else {
        const float* bo = x0;
        #pragma unroll
        for (int tm = 0; tm < 2; tm++) {
            const int t0 = m0 + warp_m * 32 + tm * 16 + g;
            #pragma unroll
            for (int tn = 0; tn < 8; tn++) {
                const int j = jb + tn * 8 + 2 * q;
                const float b0 = bo[j], b1 = bo[j + 1];
                float2 v0 = { Cf[tm][tn][0] + b0, Cf[tm][tn][1] + b1 };
                float2 v1 = { Cf[tm][tn][2] + b0, Cf[tm][tn][3] + b1 };
                *(float2*)(outp + (size_t)t0 * CC + j) = v0;
                *(float2*)(outp + (size_t)(t0 + 8) * CC + j) = v1;
            }
        }
    }
}

// ---------------- flash attention (R5 version: fat-warp tiling) ----------------
// 128 threads = 4 warps; Q block 128 rows; warp = 32 rows (2 m16 tiles) x 64 keys.
// smem (u32): Ps[128][68] @0 (Q staging then P), K[2][64][68] @8704, V[2][64][68] @17408.
#define ABUF 4352   // 64*68

__global__ __launch_bounds__(128, 2) void attn()
{
    extern __shared__ uint32_t sm[];
    uint32_t* Ps = sm;
    const uint32_t uPs = smem_u32(sm);

    const int tid = threadIdx.x;
    const int warp = tid >> 5, lane = tid & 31;
    const int g = lane >> 2, q = lane & 3;
    const int qb = 31 - blockIdx.x;    // largest work first
    const int h  = blockIdx.y;
    const int rb = warp * 32;

    const float* Qg = g_q  + (size_t)h * TT * DH + (size_t)qb * 128 * DH;
    const float* Kg = g_k  + (size_t)h * TT * DH;
    const float* Vg = g_vt + (size_t)h * DH * TT;

    const int nj = 2 * qb + 2;

    auto load_kv = [&](int j, int buf) {
        const uint32_t uK = uPs + (8704 + buf * ABUF) * 4;
        const uint32_t uV = uPs + (17408 + buf * ABUF) * 4;
        #pragma unroll
        for (int i = 0; i < 8; i++) {
            int idx = tid + i * 128; int r = idx >> 4, cc = idx & 15;
            cpa(uK + (r * 68 + cc * 4) * 4, Kg + (size_t)(j * 64 + r) * DH + cc * 4);
            cpa(uV + (r * 68 + cc * 4) * 4, Vg + (size_t)r * TT + j * 64 + cc * 4);
        }
        cp_commit();
    };

    // stage Q into Ps, prefetch KV block 0
    #pragma unroll
    for (int i = 0; i < 16; i++) {
        int idx = tid + i * 128; int r = idx >> 4, cc = idx & 15;
        cpa(uPs + (r * 68 + cc * 4) * 4, Qg + (size_t)r * DH + cc * 4);
    }
    cp_commit();
    load_kv(0, 0);
    cp_wait<0>();
    __syncthreads();

    // Q fragments -> registers
    uint32_t A[2][8][4];
    #pragma unroll
    for (int tm = 0; tm < 2; tm++) {
        const int base = rb + tm * 16;
        #pragma unroll
        for (int ks = 0; ks < 8; ks++) {
            A[tm][ks][0] = Ps[(base + g) * 68 + ks * 8 + q];
            A[tm][ks][1] = Ps[(base + 8 + g) * 68 + ks * 8 + q];
            A[tm][ks][2] = Ps[(base + g) * 68 + ks * 8 + q + 4];
            A[tm][ks][3] = Ps[(base + 8 + g) * 68 + ks * 8 + q + 4];
        }
    }
    __syncthreads();   // Ps now reusable as P

    float O[2][8][4];
    #pragma unroll
    for (int tm = 0; tm < 2; tm++)
        #pragma unroll
        for (int tn = 0; tn < 8; tn++)
            #pragma unroll
            for (int k = 0; k < 4; k++) O[tm][tn][k] = 0.f;
    float mv[4], lv[4];
    #pragma unroll
    for (int i = 0; i < 4; i++) { mv[i] = -1e30f; lv[i] = 0.f; }

    const int r0 = qb * 128 + rb + g;

    for (int j = 0; j < nj; j++) {
        if (j) { cp_wait<0>(); __syncthreads(); }
        if (j + 1 < nj) load_kv(j + 1, (j + 1) & 1);
        const uint32_t* Ks = sm + 8704 + (j & 1) * ABUF;
        const uint32_t* Vs = sm + 17408 + (j & 1) * ABUF;

        // S = Q @ K^T (log2 domain; Q pre-scaled)
        float S[2][8][4];
        #pragma unroll
        for (int tm = 0; tm < 2; tm++)
            #pragma unroll
            for (int tn = 0; tn < 8; tn++)
                #pragma unroll
                for (int k = 0; k < 4; k++) S[tm][tn][k] = 0.f;
        #pragma unroll
        for (int ks = 0; ks < 8; ks++) {
            #pragma unroll
            for (int tn = 0; tn < 8; tn++) {
                uint32_t b[2];
                b[0] = Ks[(tn * 8 + g) * 68 + ks * 8 + q];
                b[1] = Ks[(tn * 8 + g) * 68 + ks * 8 + q + 4];
                mma8(S[0][tn], A[0][ks], b);
                mma8(S[1][tn], A[1][ks], b);
            }
        }

        // causal mask (diagonal key-blocks only)
        if (j >= 2 * qb) {
            const int kb = j * 64;
            #pragma unroll
            for (int tn = 0; tn < 8; tn++) {
                const int col = kb + tn * 8 + 2 * q;
                #pragma unroll
                for (int tm = 0; tm < 2; tm++) {
                    const int ra = r0 + tm * 16, rb2 = ra + 8;
                    if (col > ra)      S[tm][tn][0] = -1e30f;
                    if (col + 1 > ra)  S[tm][tn][1] = -1e30f;
                    if (col > rb2)     S[tm][tn][2] = -1e30f;
                    if (col + 1 > rb2) S[tm][tn][3] = -1e30f;
                }
            }
        }

        // online softmax over 4 rows
        float tmax[4] = { -1e30f, -1e30f, -1e30f, -1e30f };
        #pragma unroll
        for (int tm = 0; tm < 2; tm++)
            #pragma unroll
            for (int tn = 0; tn < 8; tn++) {
                tmax[tm * 2]     = fmaxf(tmax[tm * 2],     fmaxf(S[tm][tn][0], S[tm][tn][1]));
                tmax[tm * 2 + 1] = fmaxf(tmax[tm * 2 + 1], fmaxf(S[tm][tn][2], S[tm][tn][3]));
            }
        float al[4];
        #pragma unroll
        for (int i = 0; i < 4; i++) {
            tmax[i] = fmaxf(tmax[i], __shfl_xor_sync(0xffffffffu, tmax[i], 1));
            tmax[i] = fmaxf(tmax[i], __shfl_xor_sync(0xffffffffu, tmax[i], 2));
            const float mn = fmaxf(mv[i], tmax[i]);
            al[i] = ex2(mv[i] - mn);
            mv[i] = mn;
        }
        float rs[4] = { 0.f, 0.f, 0.f, 0.f };
        #pragma unroll
        for (int tm = 0; tm < 2; tm++)
            #pragma unroll
            for (int tn = 0; tn < 8; tn++) {
                S[tm][tn][0] = ex2(S[tm][tn][0] - mv[tm * 2]);
                S[tm][tn][1] = ex2(S[tm][tn][1] - mv[tm * 2]);
                S[tm][tn][2] = ex2(S[tm][tn][2] - mv[tm * 2 + 1]);
                S[tm][tn][3] = ex2(S[tm][tn][3] - mv[tm * 2 + 1]);
                rs[tm * 2]     += S[tm][tn][0] + S[tm][tn][1];
                rs[tm * 2 + 1] += S[tm][tn][2] + S[tm][tn][3];
            }
        #pragma unroll
        for (int i = 0; i < 4; i++) {
            rs[i] += __shfl_xor_sync(0xffffffffu, rs[i], 1);
            rs[i] += __shfl_xor_sync(0xffffffffu, rs[i], 2);
            lv[i] = lv[i] * al[i] + rs[i];
        }

        // P -> smem (warp-private rows)
        #pragma unroll
        for (int tm = 0; tm < 2; tm++) {
            const int base = rb + tm * 16;
            #pragma unroll
            for (int tn = 0; tn < 8; tn++) {
                uint2 p0 = { tf32r(S[tm][tn][0]), tf32r(S[tm][tn][1]) };
                uint2 p1 = { tf32r(S[tm][tn][2]), tf32r(S[tm][tn][3]) };
                *(uint2*)(Ps + (base + g) * 68 + tn * 8 + 2 * q) = p0;
                *(uint2*)(Ps + (base + 8 + g) * 68 + tn * 8 + 2 * q) = p1;
            }
        }
        __syncwarp();

        // rescale O, accumulate P @ V
        #pragma unroll
        for (int tm = 0; tm < 2; tm++)
            #pragma unroll
            for (int tn = 0; tn < 8; tn++) {
                O[tm][tn][0] *= al[tm * 2];     O[tm][tn][1] *= al[tm * 2];
                O[tm][tn][2] *= al[tm * 2 + 1]; O[tm][tn][3] *= al[tm * 2 + 1];
            }
        #pragma unroll
        for (int ks = 0; ks < 8; ks++) {
            uint32_t a[2][4];
            #pragma unroll
            for (int tm = 0; tm < 2; tm++) {
                const int base = rb + tm * 16;
                a[tm][0] = Ps[(base + g) * 68 + ks * 8 + q];
                a[tm][1] = Ps[(base + 8 + g) * 68 + ks * 8 + q];
                a[tm][2] = Ps[(base + g) * 68 + ks * 8 + q + 4];
                a[tm][3] = Ps[(base + 8 + g) * 68 + ks * 8 + q + 4];
            }
            #pragma unroll
            for (int tn = 0; tn < 8; tn++) {
                uint32_t b[2];
                b[0] = Vs[(tn * 8 + g) * 68 + ks * 8 + q];
                b[1] = Vs[(tn * 8 + g) * 68 + ks * 8 + q + 4];
                mma8(O[0][tn], a[0], b);
                mma8(O[1][tn], a[1], b);
            }
        }
        __syncwarp();
    }

    // epilogue: normalize, tf32-round for the out-projection GEMM
    #pragma unroll
    for (int tm = 0; tm < 2; tm++) {
        const int ra = r0 + tm * 16;
        const float i0 = 1.f / lv[tm * 2], i1 = 1.f / lv[tm * 2 + 1];
        #pragma unroll
        for (int tn = 0; tn < 8; tn++) {
            const int d = tn * 8 + 2 * q;
            uint2 v0 = { tf32r(O[tm][tn][0] * i0), tf32r(O[tm][tn][1] * i0) };
            uint2 v1 = { tf32r(O[tm][tn][2] * i1), tf32r(O[tm][tn][3] * i1) };
            *(uint2*)(g_att + (size_t)ra * CC + h * DH + d) = v0;
            *(uint2*)(g_att + (size_t)(ra + 8) * CC + h * DH + d) = v1;
        }
    }
}

// ---------------- launcher ----------------
extern "C" void kernel_launch(void* const* d_in, const int* in_sizes, int n_in,
                              void* d_out, int out_size)
{
    const float* x  = (const float*)d_in[0];
    const float* wq = (const float*)d_in[1];
    const float* bq = (const float*)d_in[2];
    const float* wk = (const float*)d_in[3];
    const float* bk = (const float*)d_in[4];
    const float* wv = (const float*)d_in[5];
    const float* bv = (const float*)d_in[6];
    const float* wo = (const float*)d_in[7];
    const float* bo = (const float*)d_in[8];

    const int GSM = 3 * GBUFSZ * 4;    // 110592 B (3-stage)
    const int ASM = 26112 * 4;         // 104448 B
    cudaFuncSetAttribute(gemm_k<0>, cudaFuncAttributeMaxDynamicSharedMemorySize, GSM);
    cudaFuncSetAttribute(gemm_k<1>, cudaFuncAttributeMaxDynamicSharedMemorySize, GSM);
    cudaFuncSetAttribute(attn,      cudaFuncAttributeMaxDynamicSharedMemorySize, ASM);

    float* xt_dev;  cudaGetSymbolAddress((void**)&xt_dev,  g_xt);
    float* wt_dev;  cudaGetSymbolAddress((void**)&wt_dev,  g_wt);
    float* wot_dev; cudaGetSymbolAddress((void**)&wot_dev, g_wot);
    float* att_dev; cudaGetSymbolAddress((void**)&att_dev, g_att);

    prep<<<3648, 256>>>(x, wq, wk, wv, wo);
    gemm_k<0><<<dim3(32, 18), 256, GSM>>>(xt_dev, wt_dev, bq, bk, bv, nullptr);
    attn<<<dim3(32, 12), 128, ASM>>>();
    gemm_k<1><<<dim3(32, 6), 256, GSM>>>(att_dev, wot_dev, bo, nullptr, nullptr, (float*)d_out);
}

// round 11
// speedup vs baseline: 1.0771x; 1.0071x over previous
#include <cuda_runtime.h>
#include <cstdint>

#define TT 4096
#define CC 768
#define HH 12
#define DH 64

// ---------------- device scratch (allocation-free rule) ----------------
__device__ float g_xt [TT * CC];        // x, tf32-rounded
__device__ float g_q  [HH * TT * DH];   // [h][t][d], pre-scaled by 0.125*log2e, tf32
__device__ float g_k  [HH * TT * DH];   // [h][t][d], tf32
__device__ float g_vt [HH * DH * TT];   // [h][d][t], tf32
__device__ float g_att[TT * CC];        // concat heads, tf32
__device__ float g_wt [3 * CC * CC];    // qkv weights [j][k], tf32
__device__ float g_wot[CC * CC];        // wo as [n][k], tf32

// ---------------- helpers ----------------
static __device__ __forceinline__ uint32_t smem_u32(const void* p) {
    uint32_t a;
    asm("{ .reg .u64 t; cvta.to.shared.u64 t, %1; cvt.u32.u64 %0, t; }" : "=r"(a) : "l"(p));
    return a;
}
static __device__ __forceinline__ uint32_t tf32r(float f) {
    uint32_t u; asm("cvt.rna.tf32.f32 %0, %1;" : "=r"(u) : "f"(f)); return u;
}
static __device__ __forceinline__ float ex2(float x) {
    float y; asm("ex2.approx.f32 %0, %1;" : "=f"(y) : "f"(x)); return y;
}
static __device__ __forceinline__ void mma8(float* d, const uint32_t* a, const uint32_t* b) {
    asm volatile(
        "mma.sync.aligned.m16n8k8.row.col.f32.tf32.tf32.f32 "
        "{%0,%1,%2,%3}, {%4,%5,%6,%7}, {%8,%9}, {%0,%1,%2,%3};"
        : "+f"(d[0]), "+f"(d[1]), "+f"(d[2]), "+f"(d[3])
        : "r"(a[0]), "r"(a[1]), "r"(a[2]), "r"(a[3]), "r"(b[0]), "r"(b[1]));
}
static __device__ __forceinline__ uint4 cvt4(float4 v) {
    uint4 t; t.x = tf32r(v.x); t.y = tf32r(v.y); t.z = tf32r(v.z); t.w = tf32r(v.w);
    return t;
}
static __device__ __forceinline__ void cpa(uint32_t dst, const void* src) {
    asm volatile("cp.async.cg.shared.global [%0], [%1], 16;" :: "r"(dst), "l"(src));
}
static __device__ __forceinline__ void cp_commit() {
    asm volatile("cp.async.commit_group;" ::: "memory");
}
template <int N> static __device__ __forceinline__ void cp_wait() {
    asm volatile("cp.async.wait_group %0;" :: "n"(N) : "memory");
}
// ---- mbarrier ----
static __device__ __forceinline__ void mb_init(uint32_t a, uint32_t cnt) {
    asm volatile("mbarrier.init.shared.b64 [%0], %1;" :: "r"(a), "r"(cnt) : "memory");
}
static __device__ __forceinline__ void mb_arrive(uint32_t a) {
    asm volatile("{ .reg .b64 t; mbarrier.arrive.shared.b64 t, [%0]; }" :: "r"(a) : "memory");
}
// NOINC is load-bearing: the default form pre-increments the pending count (net-zero
// against the expected count) and the barrier never flips -> deadlock (R9/R10).
static __device__ __forceinline__ void cp_mb_arrive_noinc(uint32_t a) {
    asm volatile("cp.async.mbarrier.arrive.noinc.shared.b64 [%0];" :: "r"(a) : "memory");
}
static __device__ __forceinline__ void mb_wait(uint32_t a, uint32_t parity) {
    asm volatile(
        "{\n\t.reg .pred P1;\n\t"
        "W_%=:\n\t"
        "mbarrier.try_wait.parity.shared::cta.b64 P1, [%0], %1, 0x989680;\n\t"
        "@P1 bra D_%=;\n\t"
        "bra W_%=;\n\t"
        "D_%=:\n\t}"
        :: "r"(a), "r"(parity) : "memory");
}

// ---------------- merged preprocessing: cvt_x + 3x tr_head + tr_wo ----------------
__global__ __launch_bounds__(256) void prep(
    const float* __restrict__ x,
    const float* __restrict__ wq, const float* __restrict__ wk,
    const float* __restrict__ wv, const float* __restrict__ wo)
{
    const int b = blockIdx.x;
    if (b < 3072) {
        int i = b * 256 + threadIdx.x;
        float4 v = ((const float4*)x)[i];
        ((uint4*)g_xt)[i] = cvt4(v);
        return;
    }
    __shared__ float t[64][65];
    if (b < 3504) {
        const int bb = b - 3072;
        const int sel = bb / 144, r = bb % 144;
        const int k0 = (r % 12) * 64, h = r / 12;
        const float* src = (sel == 0) ? wq : (sel == 1) ? wk : wv;
        const float* s = src + (size_t)h * CC * DH;
        #pragma unroll
        for (int i = 0; i < 16; i++) {
            int e = threadIdx.x + i * 256; int kr = e >> 6, d = e & 63;
            t[kr][d] = s[(size_t)(k0 + kr) * DH + d];
        }
        __syncthreads();
        const int j0 = sel * CC;
        #pragma unroll
        for (int i = 0; i < 16; i++) {
            int e = threadIdx.x + i * 256; int d = e >> 6, kr = e & 63;
            g_wt[(size_t)(j0 + h * DH + d) * CC + k0 + kr] = __uint_as_float(tf32r(t[kr][d]));
        }
    } else {
        const int r = b - 3504;
        const int c0 = (r % 12) * 64, n0 = (r / 12) * 64;
        #pragma unroll
        for (int i = 0; i < 16; i++) {
            int e = threadIdx.x + i * 256; int cr = e >> 6, n = e & 63;
            t[cr][n] = wo[(size_t)(c0 + cr) * CC + n0 + n];
        }
        __syncthreads();
        #pragma unroll
        for (int i = 0; i < 16; i++) {
            int e = threadIdx.x + i * 256; int n = e >> 6, cr = e & 63;
            g_wot[(size_t)(n0 + n) * CC + c0 + cr] = __uint_as_float(tf32r(t[cr][n]));
        }
    }
}

// ---------------- GEMM (tf32 mma.sync, 3-stage cp.async): MODE 0 = qkv, 1 = out -----
#define GBUF 4608              // 128*36 u32 per matrix
#define GBUFSZ 9216            // per stage (A+B)

template <int MODE>
__global__ __launch_bounds__(256, 2) void gemm_k(
    const float* __restrict__ Am, const float* __restrict__ Bm,
    const float* __restrict__ x0, const float* __restrict__ x1,
    const float* __restrict__ x2, float* __restrict__ outp)
{
    extern __shared__ uint32_t sm[];
    const uint32_t usm = smem_u32(sm);
    const int tid = threadIdx.x;
    const int warp = tid >> 5, lane = tid & 31;
    const int g = lane >> 2, q = lane & 3;
    const int warp_m = warp & 3, warp_n = warp >> 2;
    const int m0 = blockIdx.x * 128, n0 = blockIdx.y * 128;

    auto ldgsts = [&](int k0, int buf) {
        const uint32_t uA = usm + buf * GBUFSZ * 4;
        const uint32_t uB = uA + GBUF * 4;
        #pragma unroll
        for (int i = 0; i < 4; i++) {
            int idx = tid + i * 256; int r = idx >> 3, cc = idx & 7;
            cpa(uA + (r * 36 + cc * 4) * 4, Am + (size_t)(m0 + r) * CC + k0 + cc * 4);
            cpa(uB + (r * 36 + cc * 4) * 4, Bm + (size_t)(n0 + r) * CC + k0 + cc * 4);
        }
        cp_commit();
    };

    float Cf[2][8][4];
    #pragma unroll
    for (int tm = 0; tm < 2; tm++)
        #pragma unroll
        for (int tn = 0; tn < 8; tn++)
            #pragma unroll
            for (int k = 0; k < 4; k++) Cf[tm][tn][k] = 0.f;

    ldgsts(0, 0);
    ldgsts(32, 1);

    int buf = 0;
    for (int c = 0; c < 24; c++) {
        cp_wait<1>();
        __syncthreads();
        if (c < 22) ldgsts((c + 2) * 32, (c + 2) % 3);
        const uint32_t* sA = sm + buf * GBUFSZ;
        const uint32_t* sB = sA + GBUF;
        #pragma unroll
        for (int ks = 0; ks < 4; ks++) {
            uint32_t a[2][4];
            #pragma unroll
            for (int tm = 0; tm < 2; tm++) {
                int row = warp_m * 32 + tm * 16 + g;
                a[tm][0] = sA[row * 36 + ks * 8 + q];
                a[tm][1] = sA[(row + 8) * 36 + ks * 8 + q];
                a[tm][2] = sA[row * 36 + ks * 8 + q + 4];
                a[tm][3] = sA[(row + 8) * 36 + ks * 8 + q + 4];
            }
            #pragma unroll
            for (int tn = 0; tn < 8; tn++) {
                uint32_t b[2];
                int col = warp_n * 64 + tn * 8 + g;
                b[0] = sB[col * 36 + ks * 8 + q];
                b[1] = sB[col * 36 + ks * 8 + q + 4];
                mma8(Cf[0][tn], a[0], b);
                mma8(Cf[1][tn], a[1], b);
            }
        }
        buf = (buf + 1) % 3;
    }

    const int jb = n0 + warp_n * 64;
    if (MODE == 0) {
        const float c1 = 0.18033688011112042f;   // 0.125 * log2(e)
        const int sel = jb / CC, rem = jb % CC, h = rem >> 6;
        const float* bias = (sel == 0) ? x0 : (sel == 1) ? x1 : x2;
        #pragma unroll
        for (int tm = 0; tm < 2; tm++) {
            const int t0 = m0 + warp_m * 32 + tm * 16 + g;
            #pragma unroll
            for (int tn = 0; tn < 8; tn++) {
                const int d = tn * 8 + 2 * q;
                const float b0 = bias[h * DH + d], b1 = bias[h * DH + d + 1];
                float v00 = Cf[tm][tn][0] + b0, v01 = Cf[tm][tn][1] + b1;
                float v10 = Cf[tm][tn][2] + b0, v11 = Cf[tm][tn][3] + b1;
                if (sel == 0) {
                    float* dst = g_q + (size_t)h * TT * DH;
                    uint2 p0 = { tf32r(v00 * c1), tf32r(v01 * c1) };
                    uint2 p1 = { tf32r(v10 * c1), tf32r(v11 * c1) };
                    *(uint2*)(dst + (size_t)t0 * DH + d) = p0;
                    *(uint2*)(dst + (size_t)(t0 + 8) * DH + d) = p1;
                } else if (sel == 1) {
                    float* dst = g_k + (size_t)h * TT * DH;
                    uint2 p0 = { tf32r(v00), tf32r(v01) };
                    uint2 p1 = { tf32r(v10), tf32r(v11) };
                    *(uint2*)(dst + (size_t)t0 * DH + d) = p0;
                    *(uint2*)(dst + (size_t)(t0 + 8) * DH + d) = p1;
                } else {
                    float* dst = g_vt + (size_t)h * DH * TT;
                    dst[(size_t)d * TT + t0]           = __uint_as_float(tf32r(v00));
                    dst[(size_t)(d + 1) * TT + t0]     = __uint_as_float(tf32r(v01));
                    dst[(size_t)d * TT + t0 + 8]       = __uint_as_float(tf32r(v10));
                    dst[(size_t)(d + 1) * TT + t0 + 8] = __uint_as_float(tf32r(v11));
                }
            }
        }
    } else {
        const float* bo = x0;
        #pragma unroll
        for (int tm = 0; tm < 2; tm++) {
            const int t0 = m0 + warp_m * 32 + tm * 16 + g;
            #pragma unroll
            for (int tn = 0; tn < 8; tn++) {
                const int j = jb + tn * 8 + 2 * q;
                const float b0 = bo[j], b1 = bo[j + 1];
                float2 v0 = { Cf[tm][tn][0] + b0, Cf[tm][tn][1] + b1 };
                float2 v1 = { Cf[tm][tn][2] + b0, Cf[tm][tn][3] + b1 };
                *(float2*)(outp + (size_t)t0 * CC + j) = v0;
                *(float2*)(outp + (size_t)(t0 + 8) * CC + j) = v1;
            }
        }
    }
}

// ---------------- flash attention (R5 compute + mbarrier warp-staggered sync) --------
// 128 threads = 4 warps; warp = 32 rows x 64 keys; K/V double-buffered.
// full[s] (count=128): armed by every thread's cp.async.mbarrier.arrive.NOINC after
//   issuing loads into stage s. empty[s] (count=4): lane0 of each warp arrives after
//   consuming stage s. Per-warp parity waits -> warps drift; MUFU hides under HMMA.
// smem (u32): Ps[128][68] @0, K[2][64][68] @8704, V[2][64][68] @17408.
#define ABUF 4352   // 64*68

__global__ __launch_bounds__(128, 2) void attn()
{
    extern __shared__ uint32_t sm[];
    __shared__ __align__(8) unsigned long long mbar_s[4];  // full0, full1, empty0, empty1
    uint32_t* Ps = sm;
    const uint32_t uPs = smem_u32(sm);
    const uint32_t ubar = smem_u32(mbar_s);

    const int tid = threadIdx.x;
    const int warp = tid >> 5, lane = tid & 31;
    const int g = lane >> 2, q = lane & 3;
    const int qb = 31 - blockIdx.x;    // largest work first
    const int h  = blockIdx.y;
    const int rb = warp * 32;

    const float* Qg = g_q  + (size_t)h * TT * DH + (size_t)qb * 128 * DH;
    const float* Kg = g_k  + (size_t)h * TT * DH;
    const float* Vg = g_vt + (size_t)h * DH * TT;

    const int nj = 2 * qb + 2;

    if (tid == 0) {
        mb_init(ubar + 0, 128);   // full0
        mb_init(ubar + 8, 128);   // full1
        mb_init(ubar + 16, 4);    // empty0
        mb_init(ubar + 24, 4);    // empty1
    }

    auto load_kv = [&](int j, int buf) {
        const uint32_t uK = uPs + (8704 + buf * ABUF) * 4;
        const uint32_t uV = uPs + (17408 + buf * ABUF) * 4;
        #pragma unroll
        for (int i = 0; i < 8; i++) {
            int idx = tid + i * 128; int r = idx >> 4, cc = idx & 15;
            cpa(uK + (r * 68 + cc * 4) * 4, Kg + (size_t)(j * 64 + r) * DH + cc * 4);
            cpa(uV + (r * 68 + cc * 4) * 4, Vg + (size_t)r * TT + j * 64 + cc * 4);
        }
    };

    // prologue: stage Q into Ps, load KV block 0 (classic group wait + CTA barrier;
    // this barrier also makes the mbarrier inits visible to all warps)
    #pragma unroll
    for (int i = 0; i < 16; i++) {
        int idx = tid + i * 128; int r = idx >> 4, cc = idx & 15;
        cpa(uPs + (r * 68 + cc * 4) * 4, Qg + (size_t)r * DH + cc * 4);
    }
    load_kv(0, 0);
    cp_commit();
    cp_wait<0>();
    __syncthreads();

    // Q fragments -> registers (warp-private rows)
    uint32_t A[2][8][4];
    #pragma unroll
    for (int tm = 0; tm < 2; tm++) {
        const int base = rb + tm * 16;
        #pragma unroll
        for (int ks = 0; ks < 8; ks++) {
            A[tm][ks][0] = Ps[(base + g) * 68 + ks * 8 + q];
            A[tm][ks][1] = Ps[(base + 8 + g) * 68 + ks * 8 + q];
            A[tm][ks][2] = Ps[(base + g) * 68 + ks * 8 + q + 4];
            A[tm][ks][3] = Ps[(base + 8 + g) * 68 + ks * 8 + q + 4];
        }
    }
    __syncwarp();   // Ps rows are warp-private from here on (P storage)

    float O[2][8][4];
    #pragma unroll
    for (int tm = 0; tm < 2; tm++)
        #pragma unroll
        for (int tn = 0; tn < 8; tn++)
            #pragma unroll
            for (int k = 0; k < 4; k++) O[tm][tn][k] = 0.f;
    float mv[4], lv[4];
    #pragma unroll
    for (int i = 0; i < 4; i++) { mv[i] = -1e30f; lv[i] = 0.f; }

    const int r0 = qb * 128 + rb + g;

    // per-warp parities: full start 0; empty0 starts 0, empty1 starts 1
    int pf0 = 0, pf1 = 0, pe0 = 0, pe1 = 1;

    for (int j = 0; j < nj; j++) {
        const int b = j & 1;
        if (j) {
            if (b == 0) { mb_wait(ubar + 0, pf0); pf0 ^= 1; }
            else        { mb_wait(ubar + 8, pf1); pf1 ^= 1; }
        }
        if (j + 1 < nj) {
            const int nb = (j + 1) & 1;
            if (nb == 0) { mb_wait(ubar + 16, pe0); pe0 ^= 1; }
            else         { mb_wait(ubar + 24, pe1); pe1 ^= 1; }
            load_kv(j + 1, nb);
            cp_mb_arrive_noinc(ubar + nb * 8);   // arm full[nb] (all 128 threads)
        }
        const uint32_t* Ks = sm + 8704 + b * ABUF;
        const uint32_t* Vs = sm + 17408 + b * ABUF;

        // S = Q @ K^T (log2 domain; Q pre-scaled)
        float S[2][8][4];
        #pragma unroll
        for (int tm = 0; tm < 2; tm++)
            #pragma unroll
            for (int tn = 0; tn < 8; tn++)
                #pragma unroll
                for (int k = 0; k < 4; k++) S[tm][tn][k] = 0.f;
        #pragma unroll
        for (int ks = 0; ks < 8; ks++) {
            #pragma unroll
            for (int tn = 0; tn < 8; tn++) {
                uint32_t bb[2];
                bb[0] = Ks[(tn * 8 + g) * 68 + ks * 8 + q];
                bb[1] = Ks[(tn * 8 + g) * 68 + ks * 8 + q + 4];
                mma8(S[0][tn], A[0][ks], bb);
                mma8(S[1][tn], A[1][ks], bb);
            }
        }

        // causal mask (diagonal key-blocks only)
        if (j >= 2 * qb) {
            const int kb = j * 64;
            #pragma unroll
            for (int tn = 0; tn < 8; tn++) {
                const int col = kb + tn * 8 + 2 * q;
                #pragma unroll
                for (int tm = 0; tm < 2; tm++) {
                    const int ra = r0 + tm * 16, rb2 = ra + 8;
                    if (col > ra)      S[tm][tn][0] = -1e30f;
                    if (col + 1 > ra)  S[tm][tn][1] = -1e30f;
                    if (col > rb2)     S[tm][tn][2] = -1e30f;
                    if (col + 1 > rb2) S[tm][tn][3] = -1e30f;
                }
            }
        }

        // online softmax over 4 rows
        float tmax[4] = { -1e30f, -1e30f, -1e30f, -1e30f };
        #pragma unroll
        for (int tm = 0; tm < 2; tm++)
            #pragma unroll
            for (int tn = 0; tn < 8; tn++) {
                tmax[tm * 2]     = fmaxf(tmax[tm * 2],     fmaxf(S[tm][tn][0], S[tm][tn][1]));
                tmax[tm * 2 + 1] = fmaxf(tmax[tm * 2 + 1], fmaxf(S[tm][tn][2], S[tm][tn][3]));
            }
        float al[4];
        #pragma unroll
        for (int i = 0; i < 4; i++) {
            tmax[i] = fmaxf(tmax[i], __shfl_xor_sync(0xffffffffu, tmax[i], 1));
            tmax[i] = fmaxf(tmax[i], __shfl_xor_sync(0xffffffffu, tmax[i], 2));
            const float mn = fmaxf(mv[i], tmax[i]);
            al[i] = ex2(mv[i] - mn);
            mv[i] = mn;
        }
        float rs[4] = { 0.f, 0.f, 0.f, 0.f };
        #pragma unroll
        for (int tm = 0; tm < 2; tm++)
            #pragma unroll
            for (int tn = 0; tn < 8; tn++) {
                S[tm][tn][0] = ex2(S[tm][tn][0] - mv[tm * 2]);
                S[tm][tn][1] = ex2(S[tm][tn][1] - mv[tm * 2]);
                S[tm][tn][2] = ex2(S[tm][tn][2] - mv[tm * 2 + 1]);
                S[tm][tn][3] = ex2(S[tm][tn][3] - mv[tm * 2 + 1]);
                rs[tm * 2]     += S[tm][tn][0] + S[tm][tn][1];
                rs[tm * 2 + 1] += S[tm][tn][2] + S[tm][tn][3];
            }
        #pragma unroll
        for (int i = 0; i < 4; i++) {
            rs[i] += __shfl_xor_sync(0xffffffffu, rs[i], 1);
            rs[i] += __shfl_xor_sync(0xffffffffu, rs[i], 2);
            lv[i] = lv[i] * al[i] + rs[i];
        }

        // P -> smem (warp-private rows)
        #pragma unroll
        for (int tm = 0; tm < 2; tm++) {
            const int base = rb + tm * 16;
            #pragma unroll
            for (int tn = 0; tn < 8; tn++) {
                uint2 p0 = { tf32r(S[tm][tn][0]), tf32r(S[tm][tn][1]) };
                uint2 p1 = { tf32r(S[tm][tn][2]), tf32r(S[tm][tn][3]) };
                *(uint2*)(Ps + (base + g) * 68 + tn * 8 + 2 * q) = p0;
                *(uint2*)(Ps + (base + 8 + g) * 68 + tn * 8 + 2 * q) = p1;
            }
        }
        __syncwarp();

        // rescale O, accumulate P @ V
        #pragma unroll
        for (int tm = 0; tm < 2; tm++)
            #pragma unroll
            for (int tn = 0; tn < 8; tn++) {
                O[tm][tn][0] *= al[tm * 2];     O[tm][tn][1] *= al[tm * 2];
                O[tm][tn][2] *= al[tm * 2 + 1]; O[tm][tn][3] *= al[tm * 2 + 1];
            }
        #pragma unroll
        for (int ks = 0; ks < 8; ks++) {
            uint32_t a[2][4];
            #pragma unroll
            for (int tm = 0; tm < 2; tm++) {
                const int base = rb + tm * 16;
                a[tm][0] = Ps[(base + g) * 68 + ks * 8 + q];
                a[tm][1] = Ps[(base + 8 + g) * 68 + ks * 8 + q];
                a[tm][2] = Ps[(base + g) * 68 + ks * 8 + q + 4];
                a[tm][3] = Ps[(base + 8 + g) * 68 + ks * 8 + q + 4];
            }
            #pragma unroll
            for (int tn = 0; tn < 8; tn++) {
                uint32_t bb[2];
                bb[0] = Vs[(tn * 8 + g) * 68 + ks * 8 + q];
                bb[1] = Vs[(tn * 8 + g) * 68 + ks * 8 + q + 4];
                mma8(O[0][tn], a[0], bb);
                mma8(O[1][tn], a[1], bb);
            }
        }
        __syncwarp();
        if (lane == 0) mb_arrive(ubar + 16 + b * 8);   // release stage b
    }

    // epilogue: normalize, tf32-round for the out-projection GEMM
    #pragma unroll
    for (int tm = 0; tm < 2; tm++) {
        const int ra = r0 + tm * 16;
        const float i0 = 1.f / lv[tm * 2], i1 = 1.f / lv[tm * 2 + 1];
        #pragma unroll
        for (int tn = 0; tn < 8; tn++) {
            const int d = tn * 8 + 2 * q;
            uint2 v0 = { tf32r(O[tm][tn][0] * i0), tf32r(O[tm][tn][1] * i0) };
            uint2 v1 = { tf32r(O[tm][tn][2] * i1), tf32r(O[tm][tn][3] * i1) };
            *(uint2*)(g_att + (size_t)ra * CC + h * DH + d) = v0;
            *(uint2*)(g_att + (size_t)(ra + 8) * CC + h * DH + d) = v1;
        }
    }
}

// ---------------- launcher ----------------
extern "C" void kernel_launch(void* const* d_in, const int* in_sizes, int n_in,
                              void* d_out, int out_size)
{
    const float* x  = (const float*)d_in[0];
    const float* wq = (const float*)d_in[1];
    const float* bq = (const float*)d_in[2];
    const float* wk = (const float*)d_in[3];
    const float* bk = (const float*)d_in[4];
    const float* wv = (const float*)d_in[5];
    const float* bv = (const float*)d_in[6];
    const float* wo = (const float*)d_in[7];
    const float* bo = (const float*)d_in[8];

    const int GSM = 3 * GBUFSZ * 4;    // 110592 B (3-stage)
    const int ASM = 26112 * 4;         // 104448 B
    cudaFuncSetAttribute(gemm_k<0>, cudaFuncAttributeMaxDynamicSharedMemorySize, GSM);
    cudaFuncSetAttribute(gemm_k<1>, cudaFuncAttributeMaxDynamicSharedMemorySize, GSM);
    cudaFuncSetAttribute(attn,      cudaFuncAttributeMaxDynamicSharedMemorySize, ASM);

    float* xt_dev;  cudaGetSymbolAddress((void**)&xt_dev,  g_xt);
    float* wt_dev;  cudaGetSymbolAddress((void**)&wt_dev,  g_wt);
    float* wot_dev; cudaGetSymbolAddress((void**)&wot_dev, g_wot);
    float* att_dev; cudaGetSymbolAddress((void**)&att_dev, g_att);

    prep<<<3648, 256>>>(x, wq, wk, wv, wo);
    gemm_k<0><<<dim3(32, 18), 256, GSM>>>(xt_dev, wt_dev, bq, bk, bv, nullptr);
    attn<<<dim3(32, 12), 128, ASM>>>();
    gemm_k<1><<<dim3(32, 6), 256, GSM>>>(att_dev, wot_dev, bo, nullptr, nullptr, (float*)d_out);
}

// round 12
// speedup vs baseline: 1.1746x; 1.0905x over previous
#include <cuda_runtime.h>
#include <cstdint>

#define TT 4096
#define CC 768
#define HH 12
#define DH 64

// ---------------- device scratch (allocation-free rule) ----------------
__device__ float g_xt [TT * CC];        // x, tf32-rounded
__device__ float g_q  [HH * TT * DH];   // [h][t][d], pre-scaled by 0.125*log2e, tf32
__device__ float g_k  [HH * TT * DH];   // [h][t][d], tf32
__device__ float g_vt [HH * DH * TT];   // [h][d][t], tf32
__device__ float g_att[TT * CC];        // concat heads, tf32
__device__ float g_wt [3 * CC * CC];    // qkv weights [j][k], tf32
__device__ float g_wot[CC * CC];        // wo as [n][k], tf32
// split-K attention partials (qb 16..31 -> scratch rows 0..2047 per head)
__device__ float g_po[2 * HH * 2048 * DH];   // unnormalized O per part
__device__ float g_pm[2 * HH * 2048];        // row max (log2 domain)
__device__ float g_pl[2 * HH * 2048];        // row sum

// ---------------- helpers ----------------
static __device__ __forceinline__ uint32_t smem_u32(const void* p) {
    uint32_t a;
    asm("{ .reg .u64 t; cvta.to.shared.u64 t, %1; cvt.u32.u64 %0, t; }" : "=r"(a) : "l"(p));
    return a;
}
static __device__ __forceinline__ uint32_t tf32r(float f) {
    uint32_t u; asm("cvt.rna.tf32.f32 %0, %1;" : "=r"(u) : "f"(f)); return u;
}
static __device__ __forceinline__ float ex2(float x) {
    float y; asm("ex2.approx.f32 %0, %1;" : "=f"(y) : "f"(x)); return y;
}
static __device__ __forceinline__ void mma8(float* d, const uint32_t* a, const uint32_t* b) {
    asm volatile(
        "mma.sync.aligned.m16n8k8.row.col.f32.tf32.tf32.f32 "
        "{%0,%1,%2,%3}, {%4,%5,%6,%7}, {%8,%9}, {%0,%1,%2,%3};"
        : "+f"(d[0]), "+f"(d[1]), "+f"(d[2]), "+f"(d[3])
        : "r"(a[0]), "r"(a[1]), "r"(a[2]), "r"(a[3]), "r"(b[0]), "r"(b[1]));
}
static __device__ __forceinline__ uint4 cvt4(float4 v) {
    uint4 t; t.x = tf32r(v.x); t.y = tf32r(v.y); t.z = tf32r(v.z); t.w = tf32r(v.w);
    return t;
}
static __device__ __forceinline__ void cpa(uint32_t dst, const void* src) {
    asm volatile("cp.async.cg.shared.global [%0], [%1], 16;" :: "r"(dst), "l"(src));
}
static __device__ __forceinline__ void cp_commit() {
    asm volatile("cp.async.commit_group;" ::: "memory");
}
template <int N> static __device__ __forceinline__ void cp_wait() {
    asm volatile("cp.async.wait_group %0;" :: "n"(N) : "memory");
}
// ---- mbarrier ----
static __device__ __forceinline__ void mb_init(uint32_t a, uint32_t cnt) {
    asm volatile("mbarrier.init.shared.b64 [%0], %1;" :: "r"(a), "r"(cnt) : "memory");
}
static __device__ __forceinline__ void mb_arrive(uint32_t a) {
    asm volatile("{ .reg .b64 t; mbarrier.arrive.shared.b64 t, [%0]; }" :: "r"(a) : "memory");
}
// NOINC is load-bearing: the default form pre-increments the pending count (net-zero
// against the expected count) and the barrier never flips -> deadlock (R9/R10).
static __device__ __forceinline__ void cp_mb_arrive_noinc(uint32_t a) {
    asm volatile("cp.async.mbarrier.arrive.noinc.shared.b64 [%0];" :: "r"(a) : "memory");
}
static __device__ __forceinline__ void mb_wait(uint32_t a, uint32_t parity) {
    asm volatile(
        "{\n\t.reg .pred P1;\n\t"
        "W_%=:\n\t"
        "mbarrier.try_wait.parity.shared::cta.b64 P1, [%0], %1, 0x989680;\n\t"
        "@P1 bra D_%=;\n\t"
        "bra W_%=;\n\t"
        "D_%=:\n\t}"
        :: "r"(a), "r"(parity) : "memory");
}

// ---------------- merged preprocessing: cvt_x + 3x tr_head + tr_wo ----------------
__global__ __launch_bounds__(256) void prep(
    const float* __restrict__ x,
    const float* __restrict__ wq, const float* __restrict__ wk,
    const float* __restrict__ wv, const float* __restrict__ wo)
{
    const int b = blockIdx.x;
    if (b < 3072) {
        int i = b * 256 + threadIdx.x;
        float4 v = ((const float4*)x)[i];
        ((uint4*)g_xt)[i] = cvt4(v);
        return;
    }
    __shared__ float t[64][65];
    if (b < 3504) {
        const int bb = b - 3072;
        const int sel = bb / 144, r = bb % 144;
        const int k0 = (r % 12) * 64, h = r / 12;
        const float* src = (sel == 0) ? wq : (sel == 1) ? wk : wv;
        const float* s = src + (size_t)h * CC * DH;
        #pragma unroll
        for (int i = 0; i < 16; i++) {
            int e = threadIdx.x + i * 256; int kr = e >> 6, d = e & 63;
            t[kr][d] = s[(size_t)(k0 + kr) * DH + d];
        }
        __syncthreads();
        const int j0 = sel * CC;
        #pragma unroll
        for (int i = 0; i < 16; i++) {
            int e = threadIdx.x + i * 256; int d = e >> 6, kr = e & 63;
            g_wt[(size_t)(j0 + h * DH + d) * CC + k0 + kr] = __uint_as_float(tf32r(t[kr][d]));
        }
    } else {
        const int r = b - 3504;
        const int c0 = (r % 12) * 64, n0 = (r / 12) * 64;
        #pragma unroll
        for (int i = 0; i < 16; i++) {
            int e = threadIdx.x + i * 256; int cr = e >> 6, n = e & 63;
            t[cr][n] = wo[(size_t)(c0 + cr) * CC + n0 + n];
        }
        __syncthreads();
        #pragma unroll
        for (int i = 0; i < 16; i++) {
            int e = threadIdx.x + i * 256; int n = e >> 6, cr = e & 63;
            g_wot[(size_t)(n0 + n) * CC + c0 + cr] = __uint_as_float(tf32r(t[cr][n]));
        }
    }
}

// ---------------- GEMM (tf32 mma.sync, 3-stage cp.async): MODE 0 = qkv, 1 = out -----
#define GBUF 4608              // 128*36 u32 per matrix
#define GBUFSZ 9216            // per stage (A+B)

template <int MODE>
__global__ __launch_bounds__(256, 2) void gemm_k(
    const float* __restrict__ Am, const float* __restrict__ Bm,
    const float* __restrict__ x0, const float* __restrict__ x1,
    const float* __restrict__ x2, float* __restrict__ outp)
{
    extern __shared__ uint32_t sm[];
    const uint32_t usm = smem_u32(sm);
    const int tid = threadIdx.x;
    const int warp = tid >> 5, lane = tid & 31;
    const int g = lane >> 2, q = lane & 3;
    const int warp_m = warp & 3, warp_n = warp >> 2;
    const int m0 = blockIdx.x * 128, n0 = blockIdx.y * 128;

    auto ldgsts = [&](int k0, int buf) {
        const uint32_t uA = usm + buf * GBUFSZ * 4;
        const uint32_t uB = uA + GBUF * 4;
        #pragma unroll
        for (int i = 0; i < 4; i++) {
            int idx = tid + i * 256; int r = idx >> 3, cc = idx & 7;
            cpa(uA + (r * 36 + cc * 4) * 4, Am + (size_t)(m0 + r) * CC + k0 + cc * 4);
            cpa(uB + (r * 36 + cc * 4) * 4, Bm + (size_t)(n0 + r) * CC + k0 + cc * 4);
        }
        cp_commit();
    };

    float Cf[2][8][4];
    #pragma unroll
    for (int tm = 0; tm < 2; tm++)
        #pragma unroll
        for (int tn = 0; tn < 8; tn++)
            #pragma unroll
            for (int k = 0; k < 4; k++) Cf[tm][tn][k] = 0.f;

    ldgsts(0, 0);
    ldgsts(32, 1);

    int buf = 0;
    for (int c = 0; c < 24; c++) {
        cp_wait<1>();
        __syncthreads();
        if (c < 22) ldgsts((c + 2) * 32, (c + 2) % 3);
        const uint32_t* sA = sm + buf * GBUFSZ;
        const uint32_t* sB = sA + GBUF;
        #pragma unroll
        for (int ks = 0; ks < 4; ks++) {
            uint32_t a[2][4];
            #pragma unroll
            for (int tm = 0; tm < 2; tm++) {
                int row = warp_m * 32 + tm * 16 + g;
                a[tm][0] = sA[row * 36 + ks * 8 + q];
                a[tm][1] = sA[(row + 8) * 36 + ks * 8 + q];
                a[tm][2] = sA[row * 36 + ks * 8 + q + 4];
                a[tm][3] = sA[(row + 8) * 36 + ks * 8 + q + 4];
            }
            #pragma unroll
            for (int tn = 0; tn < 8; tn++) {
                uint32_t b[2];
                int col = warp_n * 64 + tn * 8 + g;
                b[0] = sB[col * 36 + ks * 8 + q];
                b[1] = sB[col * 36 + ks * 8 + q + 4];
                mma8(Cf[0][tn], a[0], b);
                mma8(Cf[1][tn], a[1], b);
            }
        }
        buf = (buf + 1) % 3;
    }

    const int jb = n0 + warp_n * 64;
    if (MODE == 0) {
        const float c1 = 0.18033688011112042f;   // 0.125 * log2(e)
        const int sel = jb / CC, rem = jb % CC, h = rem >> 6;
        const float* bias = (sel == 0) ? x0 : (sel == 1) ? x1 : x2;
        #pragma unroll
        for (int tm = 0; tm < 2; tm++) {
            const int t0 = m0 + warp_m * 32 + tm * 16 + g;
            #pragma unroll
            for (int tn = 0; tn < 8; tn++) {
                const int d = tn * 8 + 2 * q;
                const float b0 = bias[h * DH + d], b1 = bias[h * DH + d + 1];
                float v00 = Cf[tm][tn][0] + b0, v01 = Cf[tm][tn][1] + b1;
                float v10 = Cf[tm][tn][2] + b0, v11 = Cf[tm][tn][3] + b1;
                if (sel == 0) {
                    float* dst = g_q + (size_t)h * TT * DH;
                    uint2 p0 = { tf32r(v00 * c1), tf32r(v01 * c1) };
                    uint2 p1 = { tf32r(v10 * c1), tf32r(v11 * c1) };
                    *(uint2*)(dst + (size_t)t0 * DH + d) = p0;
                    *(uint2*)(dst + (size_t)(t0 + 8) * DH + d) = p1;
                } else if (sel == 1) {
                    float* dst = g_k + (size_t)h * TT * DH;
                    uint2 p0 = { tf32r(v00), tf32r(v01) };
                    uint2 p1 = { tf32r(v10), tf32r(v11) };
                    *(uint2*)(dst + (size_t)t0 * DH + d) = p0;
                    *(uint2*)(dst + (size_t)(t0 + 8) * DH + d) = p1;
                } else {
                    float* dst = g_vt + (size_t)h * DH * TT;
                    dst[(size_t)d * TT + t0]           = __uint_as_float(tf32r(v00));
                    dst[(size_t)(d + 1) * TT + t0]     = __uint_as_float(tf32r(v01));
                    dst[(size_t)d * TT + t0 + 8]       = __uint_as_float(tf32r(v10));
                    dst[(size_t)(d + 1) * TT + t0 + 8] = __uint_as_float(tf32r(v11));
                }
            }
        }
    } else {
        const float* bo = x0;
        #pragma unroll
        for (int tm = 0; tm < 2; tm++) {
            const int t0 = m0 + warp_m * 32 + tm * 16 + g;
            #pragma unroll
            for (int tn = 0; tn < 8; tn++) {
                const int j = jb + tn * 8 + 2 * q;
                const float b0 = bo[j], b1 = bo[j + 1];
                float2 v0 = { Cf[tm][tn][0] + b0, Cf[tm][tn][1] + b1 };
                float2 v1 = { Cf[tm][tn][2] + b0, Cf[tm][tn][3] + b1 };
                *(float2*)(outp + (size_t)t0 * CC + j) = v0;
                *(float2*)(outp + (size_t)(t0 + 8) * CC + j) = v1;
            }
        }
    }
}

// ---------------- flash attention (split-K over key blocks for large qb) -------------
// grid.x = 48: bx<32 -> qb = 31-bx/2 (>=16), part = bx&1 (half the key range each);
//              bx>=32 -> qb = 47-bx (<16), unsplit. Largest work first.
// Split parts write unnormalized O + (m,l) to scratch; merge_k recombines.
// Pipeline/compute identical to R11 (mbarrier-staggered, warp = 32 rows).
#define ABUF 4352   // 64*68

__global__ __launch_bounds__(128, 2) void attn()
{
    extern __shared__ uint32_t sm[];
    __shared__ __align__(8) unsigned long long mbar_s[4];  // full0, full1, empty0, empty1
    uint32_t* Ps = sm;
    const uint32_t uPs = smem_u32(sm);
    const uint32_t ubar = smem_u32(mbar_s);

    const int tid = threadIdx.x;
    const int warp = tid >> 5, lane = tid & 31;
    const int g = lane >> 2, q = lane & 3;
    const int h = blockIdx.y;
    const int rb = warp * 32;

    const int bx = blockIdx.x;
    int qb, part, j0, j1;
    if (bx < 32) {
        qb = 31 - (bx >> 1); part = bx & 1;
        const int half = qb + 1;
        j0 = part ? half : 0;
        j1 = part ? (2 * qb + 2) : half;
    } else {
        qb = 47 - bx; part = -1;
        j0 = 0; j1 = 2 * qb + 2;
    }
    const int nloc = j1 - j0;

    const float* Qg = g_q  + (size_t)h * TT * DH + (size_t)qb * 128 * DH;
    const float* Kg = g_k  + (size_t)h * TT * DH;
    const float* Vg = g_vt + (size_t)h * DH * TT;

    if (tid == 0) {
        mb_init(ubar + 0, 128);   // full0
        mb_init(ubar + 8, 128);   // full1
        mb_init(ubar + 16, 4);    // empty0
        mb_init(ubar + 24, 4);    // empty1
    }

    auto load_kv = [&](int j, int buf) {
        const uint32_t uK = uPs + (8704 + buf * ABUF) * 4;
        const uint32_t uV = uPs + (17408 + buf * ABUF) * 4;
        #pragma unroll
        for (int i = 0; i < 8; i++) {
            int idx = tid + i * 128; int r = idx >> 4, cc = idx & 15;
            cpa(uK + (r * 68 + cc * 4) * 4, Kg + (size_t)(j * 64 + r) * DH + cc * 4);
            cpa(uV + (r * 68 + cc * 4) * 4, Vg + (size_t)r * TT + j * 64 + cc * 4);
        }
    };

    // prologue: stage Q into Ps, load first KV block (group wait + CTA barrier,
    // which also publishes the mbarrier inits)
    #pragma unroll
    for (int i = 0; i < 16; i++) {
        int idx = tid + i * 128; int r = idx >> 4, cc = idx & 15;
        cpa(uPs + (r * 68 + cc * 4) * 4, Qg + (size_t)r * DH + cc * 4);
    }
    load_kv(j0, 0);
    cp_commit();
    cp_wait<0>();
    __syncthreads();

    // Q fragments -> registers (warp-private rows)
    uint32_t A[2][8][4];
    #pragma unroll
    for (int tm = 0; tm < 2; tm++) {
        const int base = rb + tm * 16;
        #pragma unroll
        for (int ks = 0; ks < 8; ks++) {
            A[tm][ks][0] = Ps[(base + g) * 68 + ks * 8 + q];
            A[tm][ks][1] = Ps[(base + 8 + g) * 68 + ks * 8 + q];
            A[tm][ks][2] = Ps[(base + g) * 68 + ks * 8 + q + 4];
            A[tm][ks][3] = Ps[(base + 8 + g) * 68 + ks * 8 + q + 4];
        }
    }
    __syncwarp();   // Ps rows are warp-private from here on (P storage)

    float O[2][8][4];
    #pragma unroll
    for (int tm = 0; tm < 2; tm++)
        #pragma unroll
        for (int tn = 0; tn < 8; tn++)
            #pragma unroll
            for (int k = 0; k < 4; k++) O[tm][tn][k] = 0.f;
    float mv[4], lv[4];
    #pragma unroll
    for (int i = 0; i < 4; i++) { mv[i] = -1e30f; lv[i] = 0.f; }

    const int r0 = qb * 128 + rb + g;

    // per-warp parities: full start 0; empty0 starts 0, empty1 starts 1
    int pf0 = 0, pf1 = 0, pe0 = 0, pe1 = 1;

    for (int jj = 0; jj < nloc; jj++) {
        const int j = j0 + jj;
        const int b = jj & 1;
        if (jj) {
            if (b == 0) { mb_wait(ubar + 0, pf0); pf0 ^= 1; }
            else        { mb_wait(ubar + 8, pf1); pf1 ^= 1; }
        }
        if (jj + 1 < nloc) {
            const int nb = (jj + 1) & 1;
            if (nb == 0) { mb_wait(ubar + 16, pe0); pe0 ^= 1; }
            else         { mb_wait(ubar + 24, pe1); pe1 ^= 1; }
            load_kv(j + 1, nb);
            cp_mb_arrive_noinc(ubar + nb * 8);   // arm full[nb] (all 128 threads)
        }
        const uint32_t* Ks = sm + 8704 + b * ABUF;
        const uint32_t* Vs = sm + 17408 + b * ABUF;

        // S = Q @ K^T (log2 domain; Q pre-scaled)
        float S[2][8][4];
        #pragma unroll
        for (int tm = 0; tm < 2; tm++)
            #pragma unroll
            for (int tn = 0; tn < 8; tn++)
                #pragma unroll
                for (int k = 0; k < 4; k++) S[tm][tn][k] = 0.f;
        #pragma unroll
        for (int ks = 0; ks < 8; ks++) {
            #pragma unroll
            for (int tn = 0; tn < 8; tn++) {
                uint32_t bb[2];
                bb[0] = Ks[(tn * 8 + g) * 68 + ks * 8 + q];
                bb[1] = Ks[(tn * 8 + g) * 68 + ks * 8 + q + 4];
                mma8(S[0][tn], A[0][ks], bb);
                mma8(S[1][tn], A[1][ks], bb);
            }
        }

        // causal mask (diagonal key-blocks only; j is absolute)
        if (j >= 2 * qb) {
            const int kb = j * 64;
            #pragma unroll
            for (int tn = 0; tn < 8; tn++) {
                const int col = kb + tn * 8 + 2 * q;
                #pragma unroll
                for (int tm = 0; tm < 2; tm++) {
                    const int ra = r0 + tm * 16, rb2 = ra + 8;
                    if (col > ra)      S[tm][tn][0] = -1e30f;
                    if (col + 1 > ra)  S[tm][tn][1] = -1e30f;
                    if (col > rb2)     S[tm][tn][2] = -1e30f;
                    if (col + 1 > rb2) S[tm][tn][3] = -1e30f;
                }
            }
        }

        // online softmax over 4 rows
        float tmax[4] = { -1e30f, -1e30f, -1e30f, -1e30f };
        #pragma unroll
        for (int tm = 0; tm < 2; tm++)
            #pragma unroll
            for (int tn = 0; tn < 8; tn++) {
                tmax[tm * 2]     = fmaxf(tmax[tm * 2],     fmaxf(S[tm][tn][0], S[tm][tn][1]));
                tmax[tm * 2 + 1] = fmaxf(tmax[tm * 2 + 1], fmaxf(S[tm][tn][2], S[tm][tn][3]));
            }
        float al[4];
        #pragma unroll
        for (int i = 0; i < 4; i++) {
            tmax[i] = fmaxf(tmax[i], __shfl_xor_sync(0xffffffffu, tmax[i], 1));
            tmax[i] = fmaxf(tmax[i], __shfl_xor_sync(0xffffffffu, tmax[i], 2));
            const float mn = fmaxf(mv[i], tmax[i]);
            al[i] = ex2(mv[i] - mn);
            mv[i] = mn;
        }
        float rs[4] = { 0.f, 0.f, 0.f, 0.f };
        #pragma unroll
        for (int tm = 0; tm < 2; tm++)
            #pragma unroll
            for (int tn = 0; tn < 8; tn++) {
                S[tm][tn][0] = ex2(S[tm][tn][0] - mv[tm * 2]);
                S[tm][tn][1] = ex2(S[tm][tn][1] - mv[tm * 2]);
                S[tm][tn][2] = ex2(S[tm][tn][2] - mv[tm * 2 + 1]);
                S[tm][tn][3] = ex2(S[tm][tn][3] - mv[tm * 2 + 1]);
                rs[tm * 2]     += S[tm][tn][0] + S[tm][tn][1];
                rs[tm * 2 + 1] += S[tm][tn][2] + S[tm][tn][3];
            }
        #pragma unroll
        for (int i = 0; i < 4; i++) {
            rs[i] += __shfl_xor_sync(0xffffffffu, rs[i], 1);
            rs[i] += __shfl_xor_sync(0xffffffffu, rs[i], 2);
            lv[i] = lv[i] * al[i] + rs[i];
        }

        // P -> smem (warp-private rows)
        #pragma unroll
        for (int tm = 0; tm < 2; tm++) {
            const int base = rb + tm * 16;
            #pragma unroll
            for (int tn = 0; tn < 8; tn++) {
                uint2 p0 = { tf32r(S[tm][tn][0]), tf32r(S[tm][tn][1]) };
                uint2 p1 = { tf32r(S[tm][tn][2]), tf32r(S[tm][tn][3]) };
                *(uint2*)(Ps + (base + g) * 68 + tn * 8 + 2 * q) = p0;
                *(uint2*)(Ps + (base + 8 + g) * 68 + tn * 8 + 2 * q) = p1;
            }
        }
        __syncwarp();

        // rescale O, accumulate P @ V
        #pragma unroll
        for (int tm = 0; tm < 2; tm++)
            #pragma unroll
            for (int tn = 0; tn < 8; tn++) {
                O[tm][tn][0] *= al[tm * 2];     O[tm][tn][1] *= al[tm * 2];
                O[tm][tn][2] *= al[tm * 2 + 1]; O[tm][tn][3] *= al[tm * 2 + 1];
            }
        #pragma unroll
        for (int ks = 0; ks < 8; ks++) {
            uint32_t a[2][4];
            #pragma unroll
            for (int tm = 0; tm < 2; tm++) {
                const int base = rb + tm * 16;
                a[tm][0] = Ps[(base + g) * 68 + ks * 8 + q];
                a[tm][1] = Ps[(base + 8 + g) * 68 + ks * 8 + q];
                a[tm][2] = Ps[(base + g) * 68 + ks * 8 + q + 4];
                a[tm][3] = Ps[(base + 8 + g) * 68 + ks * 8 + q + 4];
            }
            #pragma unroll
            for (int tn = 0; tn < 8; tn++) {
                uint32_t bb[2];
                bb[0] = Vs[(tn * 8 + g) * 68 + ks * 8 + q];
                bb[1] = Vs[(tn * 8 + g) * 68 + ks * 8 + q + 4];
                mma8(O[0][tn], a[0], bb);
                mma8(O[1][tn], a[1], bb);
            }
        }
        __syncwarp();
        if (lane == 0) mb_arrive(ubar + 16 + b * 8);   // release stage b
    }

    if (part < 0) {
        // unsplit: normalize and write g_att (tf32-rounded for the out GEMM)
        #pragma unroll
        for (int tm = 0; tm < 2; tm++) {
            const int ra = r0 + tm * 16;
            const float i0 = 1.f / lv[tm * 2], i1 = 1.f / lv[tm * 2 + 1];
            #pragma unroll
            for (int tn = 0; tn < 8; tn++) {
                const int d = tn * 8 + 2 * q;
                uint2 v0 = { tf32r(O[tm][tn][0] * i0), tf32r(O[tm][tn][1] * i0) };
                uint2 v1 = { tf32r(O[tm][tn][2] * i1), tf32r(O[tm][tn][3] * i1) };
                *(uint2*)(g_att + (size_t)ra * CC + h * DH + d) = v0;
                *(uint2*)(g_att + (size_t)(ra + 8) * CC + h * DH + d) = v1;
            }
        }
    } else {
        // split: write unnormalized O + (m, l) to scratch
        const int sb = (qb - 16) * 128;
        float* poB = g_po + ((size_t)part * HH + h) * 2048 * 64;
        #pragma unroll
        for (int tm = 0; tm < 2; tm++) {
            const int lr = rb + tm * 16 + g;
            #pragma unroll
            for (int tn = 0; tn < 8; tn++) {
                const int d = tn * 8 + 2 * q;
                float2 v0 = { O[tm][tn][0], O[tm][tn][1] };
                float2 v1 = { O[tm][tn][2], O[tm][tn][3] };
                *(float2*)(poB + (size_t)(sb + lr) * 64 + d) = v0;
                *(float2*)(poB + (size_t)(sb + lr + 8) * 64 + d) = v1;
            }
            if (q == 0) {
                const size_t mi = ((size_t)part * HH + h) * 2048 + sb;
                g_pm[mi + lr]     = mv[tm * 2];     g_pl[mi + lr]     = lv[tm * 2];
                g_pm[mi + lr + 8] = mv[tm * 2 + 1]; g_pl[mi + lr + 8] = lv[tm * 2 + 1];
            }
        }
    }
}

// ---------------- merge split-K partials (token rows 2048..4095) ----------------
__global__ __launch_bounds__(256) void merge_k()
{
    const int idx = blockIdx.x * 256 + threadIdx.x;   // 12 * 2048 * 16 = 393216
    const int d4  = (idx & 15) * 4;
    const int row = (idx >> 4) & 2047;
    const int h   = idx >> 15;

    const size_t mi = (size_t)h * 2048 + row;
    const float m1 = g_pm[mi],                  l1 = g_pl[mi];
    const float m2 = g_pm[(size_t)HH * 2048 + mi], l2 = g_pl[(size_t)HH * 2048 + mi];
    const float m  = fmaxf(m1, m2);
    const float w1 = ex2(m1 - m), w2 = ex2(m2 - m);
    const float inv = 1.f / (l1 * w1 + l2 * w2);

    const size_t oi = ((size_t)h * 2048 + row) * 64 + d4;
    const float4 o1 = *(const float4*)(g_po + oi);
    const float4 o2 = *(const float4*)(g_po + (size_t)HH * 2048 * 64 + oi);
    uint4 r;
    r.x = tf32r((o1.x * w1 + o2.x * w2) * inv);
    r.y = tf32r((o1.y * w1 + o2.y * w2) * inv);
    r.z = tf32r((o1.z * w1 + o2.z * w2) * inv);
    r.w = tf32r((o1.w * w1 + o2.w * w2) * inv);

    const int tok = 2048 + row;
    *(uint4*)(g_att + (size_t)tok * CC + h * DH + d4) = r;
}

// ---------------- launcher ----------------
extern "C" void kernel_launch(void* const* d_in, const int* in_sizes, int n_in,
                              void* d_out, int out_size)
{
    const float* x  = (const float*)d_in[0];
    const float* wq = (const float*)d_in[1];
    const float* bq = (const float*)d_in[2];
    const float* wk = (const float*)d_in[3];
    const float* bk = (const float*)d_in[4];
    const float* wv = (const float*)d_in[5];
    const float* bv = (const float*)d_in[6];
    const float* wo = (const float*)d_in[7];
    const float* bo = (const float*)d_in[8];

    const int GSM = 3 * GBUFSZ * 4;    // 110592 B (3-stage)
    const int ASM = 26112 * 4;         // 104448 B
    cudaFuncSetAttribute(gemm_k<0>, cudaFuncAttributeMaxDynamicSharedMemorySize, GSM);
    cudaFuncSetAttribute(gemm_k<1>, cudaFuncAttributeMaxDynamicSharedMemorySize, GSM);
    cudaFuncSetAttribute(attn,      cudaFuncAttributeMaxDynamicSharedMemorySize, ASM);

    float* xt_dev;  cudaGetSymbolAddress((void**)&xt_dev,  g_xt);
    float* wt_dev;  cudaGetSymbolAddress((void**)&wt_dev,  g_wt);
    float* wot_dev; cudaGetSymbolAddress((void**)&wot_dev, g_wot);
    float* att_dev; cudaGetSymbolAddress((void**)&att_dev, g_att);

    prep<<<3648, 256>>>(x, wq, wk, wv, wo);
    gemm_k<0><<<dim3(32, 18), 256, GSM>>>(xt_dev, wt_dev, bq, bk, bv, nullptr);
    attn<<<dim3(48, 12), 128, ASM>>>();
    merge_k<<<1536, 256>>>();
    gemm_k<1><<<dim3(32, 6), 256, GSM>>>(att_dev, wot_dev, bo, nullptr, nullptr, (float*)d_out);
}

// round 13
// speedup vs baseline: 1.2449x; 1.0599x over previous
#include <cuda_runtime.h>
#include <cstdint>

#define TT 4096
#define CC 768
#define HH 12
#define DH 64

// ---------------- device scratch (allocation-free rule) ----------------
__device__ float g_xt [TT * CC];        // x, tf32-rounded
__device__ float g_q  [HH * TT * DH];   // [h][t][d], pre-scaled by 0.125*log2e, tf32
__device__ float g_k  [HH * TT * DH];   // [h][t][d], tf32
__device__ float g_vt [HH * DH * TT];   // [h][d][t], tf32
__device__ float g_att[TT * CC];        // concat heads, tf32
__device__ float g_wt [3 * CC * CC];    // qkv weights [j][k], tf32
__device__ float g_wot[CC * CC];        // wo as [n][k], tf32
// split-K attention partials (qb 8..31 -> scratch rows 0..3071 per head, up to 4 parts)
__device__ float g_po[4 * HH * 3072 * DH];   // unnormalized O per part
__device__ float g_pm[4 * HH * 3072];        // row max (log2 domain)
__device__ float g_pl[4 * HH * 3072];        // row sum

// ---------------- helpers ----------------
static __device__ __forceinline__ uint32_t smem_u32(const void* p) {
    uint32_t a;
    asm("{ .reg .u64 t; cvta.to.shared.u64 t, %1; cvt.u32.u64 %0, t; }" : "=r"(a) : "l"(p));
    return a;
}
static __device__ __forceinline__ uint32_t tf32r(float f) {
    uint32_t u; asm("cvt.rna.tf32.f32 %0, %1;" : "=r"(u) : "f"(f)); return u;
}
static __device__ __forceinline__ float ex2(float x) {
    float y; asm("ex2.approx.f32 %0, %1;" : "=f"(y) : "f"(x)); return y;
}
static __device__ __forceinline__ void mma8(float* d, const uint32_t* a, const uint32_t* b) {
    asm volatile(
        "mma.sync.aligned.m16n8k8.row.col.f32.tf32.tf32.f32 "
        "{%0,%1,%2,%3}, {%4,%5,%6,%7}, {%8,%9}, {%0,%1,%2,%3};"
        : "+f"(d[0]), "+f"(d[1]), "+f"(d[2]), "+f"(d[3])
        : "r"(a[0]), "r"(a[1]), "r"(a[2]), "r"(a[3]), "r"(b[0]), "r"(b[1]));
}
static __device__ __forceinline__ uint4 cvt4(float4 v) {
    uint4 t; t.x = tf32r(v.x); t.y = tf32r(v.y); t.z = tf32r(v.z); t.w = tf32r(v.w);
    return t;
}
static __device__ __forceinline__ void cpa(uint32_t dst, const void* src) {
    asm volatile("cp.async.cg.shared.global [%0], [%1], 16;" :: "r"(dst), "l"(src));
}
static __device__ __forceinline__ void cp_commit() {
    asm volatile("cp.async.commit_group;" ::: "memory");
}
template <int N> static __device__ __forceinline__ void cp_wait() {
    asm volatile("cp.async.wait_group %0;" :: "n"(N) : "memory");
}
// ---- mbarrier ----
static __device__ __forceinline__ void mb_init(uint32_t a, uint32_t cnt) {
    asm volatile("mbarrier.init.shared.b64 [%0], %1;" :: "r"(a), "r"(cnt) : "memory");
}
static __device__ __forceinline__ void mb_arrive(uint32_t a) {
    asm volatile("{ .reg .b64 t; mbarrier.arrive.shared.b64 t, [%0]; }" :: "r"(a) : "memory");
}
// NOINC is load-bearing: the default form pre-increments the pending count (net-zero
// against the expected count) and the barrier never flips -> deadlock (R9/R10).
static __device__ __forceinline__ void cp_mb_arrive_noinc(uint32_t a) {
    asm volatile("cp.async.mbarrier.arrive.noinc.shared.b64 [%0];" :: "r"(a) : "memory");
}
static __device__ __forceinline__ void mb_wait(uint32_t a, uint32_t parity) {
    asm volatile(
        "{\n\t.reg .pred P1;\n\t"
        "W_%=:\n\t"
        "mbarrier.try_wait.parity.shared::cta.b64 P1, [%0], %1, 0x989680;\n\t"
        "@P1 bra D_%=;\n\t"
        "bra W_%=;\n\t"
        "D_%=:\n\t}"
        :: "r"(a), "r"(parity) : "memory");
}

// ---------------- merged preprocessing: cvt_x + 3x tr_head + tr_wo ----------------
__global__ __launch_bounds__(256) void prep(
    const float* __restrict__ x,
    const float* __restrict__ wq, const float* __restrict__ wk,
    const float* __restrict__ wv, const float* __restrict__ wo)
{
    const int b = blockIdx.x;
    if (b < 3072) {
        int i = b * 256 + threadIdx.x;
        float4 v = ((const float4*)x)[i];
        ((uint4*)g_xt)[i] = cvt4(v);
        return;
    }
    __shared__ float t[64][65];
    if (b < 3504) {
        const int bb = b - 3072;
        const int sel = bb / 144, r = bb % 144;
        const int k0 = (r % 12) * 64, h = r / 12;
        const float* src = (sel == 0) ? wq : (sel == 1) ? wk : wv;
        const float* s = src + (size_t)h * CC * DH;
        #pragma unroll
        for (int i = 0; i < 16; i++) {
            int e = threadIdx.x + i * 256; int kr = e >> 6, d = e & 63;
            t[kr][d] = s[(size_t)(k0 + kr) * DH + d];
        }
        __syncthreads();
        const int j0 = sel * CC;
        #pragma unroll
        for (int i = 0; i < 16; i++) {
            int e = threadIdx.x + i * 256; int d = e >> 6, kr = e & 63;
            g_wt[(size_t)(j0 + h * DH + d) * CC + k0 + kr] = __uint_as_float(tf32r(t[kr][d]));
        }
    } else {
        const int r = b - 3504;
        const int c0 = (r % 12) * 64, n0 = (r / 12) * 64;
        #pragma unroll
        for (int i = 0; i < 16; i++) {
            int e = threadIdx.x + i * 256; int cr = e >> 6, n = e & 63;
            t[cr][n] = wo[(size_t)(c0 + cr) * CC + n0 + n];
        }
        __syncthreads();
        #pragma unroll
        for (int i = 0; i < 16; i++) {
            int e = threadIdx.x + i * 256; int n = e >> 6, cr = e & 63;
            g_wot[(size_t)(n0 + n) * CC + c0 + cr] = __uint_as_float(tf32r(t[cr][n]));
        }
    }
}

// ---------------- GEMM (tf32 mma.sync, 3-stage cp.async): MODE 0 = qkv, 1 = out -----
#define GBUF 4608              // 128*36 u32 per matrix
#define GBUFSZ 9216            // per stage (A+B)

template <int MODE>
__global__ __launch_bounds__(256, 2) void gemm_k(
    const float* __restrict__ Am, const float* __restrict__ Bm,
    const float* __restrict__ x0, const float* __restrict__ x1,
    const float* __restrict__ x2, float* __restrict__ outp)
{
    extern __shared__ uint32_t sm[];
    const uint32_t usm = smem_u32(sm);
    const int tid = threadIdx.x;
    const int warp = tid >> 5, lane = tid & 31;
    const int g = lane >> 2, q = lane & 3;
    const int warp_m = warp & 3, warp_n = warp >> 2;
    const int m0 = blockIdx.x * 128, n0 = blockIdx.y * 128;

    auto ldgsts = [&](int k0, int buf) {
        const uint32_t uA = usm + buf * GBUFSZ * 4;
        const uint32_t uB = uA + GBUF * 4;
        #pragma unroll
        for (int i = 0; i < 4; i++) {
            int idx = tid + i * 256; int r = idx >> 3, cc = idx & 7;
            cpa(uA + (r * 36 + cc * 4) * 4, Am + (size_t)(m0 + r) * CC + k0 + cc * 4);
            cpa(uB + (r * 36 + cc * 4) * 4, Bm + (size_t)(n0 + r) * CC + k0 + cc * 4);
        }
        cp_commit();
    };

    float Cf[2][8][4];
    #pragma unroll
    for (int tm = 0; tm < 2; tm++)
        #pragma unroll
        for (int tn = 0; tn < 8; tn++)
            #pragma unroll
            for (int k = 0; k < 4; k++) Cf[tm][tn][k] = 0.f;

    ldgsts(0, 0);
    ldgsts(32, 1);

    int buf = 0;
    for (int c = 0; c < 24; c++) {
        cp_wait<1>();
        __syncthreads();
        if (c < 22) ldgsts((c + 2) * 32, (c + 2) % 3);
        const uint32_t* sA = sm + buf * GBUFSZ;
        const uint32_t* sB = sA + GBUF;
        #pragma unroll
        for (int ks = 0; ks < 4; ks++) {
            uint32_t a[2][4];
            #pragma unroll
            for (int tm = 0; tm < 2; tm++) {
                int row = warp_m * 32 + tm * 16 + g;
                a[tm][0] = sA[row * 36 + ks * 8 + q];
                a[tm][1] = sA[(row + 8) * 36 + ks * 8 + q];
                a[tm][2] = sA[row * 36 + ks * 8 + q + 4];
                a[tm][3] = sA[(row + 8) * 36 + ks * 8 + q + 4];
            }
            #pragma unroll
            for (int tn = 0; tn < 8; tn++) {
                uint32_t b[2];
                int col = warp_n * 64 + tn * 8 + g;
                b[0] = sB[col * 36 + ks * 8 + q];
                b[1] = sB[col * 36 + ks * 8 + q + 4];
                mma8(Cf[0][tn], a[0], b);
                mma8(Cf[1][tn], a[1], b);
            }
        }
        buf = (buf + 1) % 3;
    }

    const int jb = n0 + warp_n * 64;
    if (MODE == 0) {
        const float c1 = 0.18033688011112042f;   // 0.125 * log2(e)
        const int sel = jb / CC, rem = jb % CC, h = rem >> 6;
        const float* bias = (sel == 0) ? x0 : (sel == 1) ? x1 : x2;
        #pragma unroll
        for (int tm = 0; tm < 2; tm++) {
            const int t0 = m0 + warp_m * 32 + tm * 16 + g;
            #pragma unroll
            for (int tn = 0; tn < 8; tn++) {
                const int d = tn * 8 + 2 * q;
                const float b0 = bias[h * DH + d], b1 = bias[h * DH + d + 1];
                float v00 = Cf[tm][tn][0] + b0, v01 = Cf[tm][tn][1] + b1;
                float v10 = Cf[tm][tn][2] + b0, v11 = Cf[tm][tn][3] + b1;
                if (sel == 0) {
                    float* dst = g_q + (size_t)h * TT * DH;
                    uint2 p0 = { tf32r(v00 * c1), tf32r(v01 * c1) };
                    uint2 p1 = { tf32r(v10 * c1), tf32r(v11 * c1) };
                    *(uint2*)(dst + (size_t)t0 * DH + d) = p0;
                    *(uint2*)(dst + (size_t)(t0 + 8) * DH + d) = p1;
                } else if (sel == 1) {
                    float* dst = g_k + (size_t)h * TT * DH;
                    uint2 p0 = { tf32r(v00), tf32r(v01) };
                    uint2 p1 = { tf32r(v10), tf32r(v11) };
                    *(uint2*)(dst + (size_t)t0 * DH + d) = p0;
                    *(uint2*)(dst + (size_t)(t0 + 8) * DH + d) = p1;
                } else {
                    float* dst = g_vt + (size_t)h * DH * TT;
                    dst[(size_t)d * TT + t0]           = __uint_as_float(tf32r(v00));
                    dst[(size_t)(d + 1) * TT + t0]     = __uint_as_float(tf32r(v01));
                    dst[(size_t)d * TT + t0 + 8]       = __uint_as_float(tf32r(v10));
                    dst[(size_t)(d + 1) * TT + t0 + 8] = __uint_as_float(tf32r(v11));
                }
            }
        }
    } else {
        const float* bo = x0;
        #pragma unroll
        for (int tm = 0; tm < 2; tm++) {
            const int t0 = m0 + warp_m * 32 + tm * 16 + g;
            #pragma unroll
            for (int tn = 0; tn < 8; tn++) {
                const int j = jb + tn * 8 + 2 * q;
                const float b0 = bo[j], b1 = bo[j + 1];
                float2 v0 = { Cf[tm][tn][0] + b0, Cf[tm][tn][1] + b1 };
                float2 v1 = { Cf[tm][tn][2] + b0, Cf[tm][tn][3] + b1 };
                *(float2*)(outp + (size_t)t0 * CC + j) = v0;
                *(float2*)(outp + (size_t)(t0 + 8) * CC + j) = v1;
            }
        }
    }
}

// ---------------- flash attention (fine split-K: parts of <=16 key-blocks) -----------
// grid.x = 80 (per head), descending work:
//   bx [0,32):  qb = 31 - bx/4, np=4   (W=50..64 -> parts 12..16)
//   bx [32,56): qb = 23 - (bx-32)/3, np=3   (W=34..48 -> parts 11..16)
//   bx [56,72): qb = 15 - (bx-56)/2, np=2   (W=18..32 -> parts 9..16)
//   bx [72,80): qb = 7 - (bx-72),   np=1   (W=2..16, direct write)
// Part key-range: [W*p/np, W*(p+1)/np). Split parts write unnormalized O + (m,l).
#define ABUF 4352   // 64*68

__global__ __launch_bounds__(128, 2) void attn()
{
    extern __shared__ uint32_t sm[];
    __shared__ __align__(8) unsigned long long mbar_s[4];  // full0, full1, empty0, empty1
    uint32_t* Ps = sm;
    const uint32_t uPs = smem_u32(sm);
    const uint32_t ubar = smem_u32(mbar_s);

    const int tid = threadIdx.x;
    const int warp = tid >> 5, lane = tid & 31;
    const int g = lane >> 2, q = lane & 3;
    const int h = blockIdx.y;
    const int rb = warp * 32;

    const int bx = blockIdx.x;
    int qb, part, np;
    if (bx < 32)      { qb = 31 - (bx >> 2);        part = bx & 3;        np = 4; }
    else if (bx < 56) { int t = bx - 32; qb = 23 - t / 3; part = t % 3;   np = 3; }
    else if (bx < 72) { int t = bx - 56; qb = 15 - (t >> 1); part = t & 1; np = 2; }
    else              { qb = 7 - (bx - 72);          part = 0;            np = 1; }
    const int W  = 2 * qb + 2;
    const int j0 = (W * part) / np;
    const int j1 = (W * (part + 1)) / np;
    const int nloc = j1 - j0;
    const bool split = (np > 1);

    const float* Qg = g_q  + (size_t)h * TT * DH + (size_t)qb * 128 * DH;
    const float* Kg = g_k  + (size_t)h * TT * DH;
    const float* Vg = g_vt + (size_t)h * DH * TT;

    if (tid == 0) {
        mb_init(ubar + 0, 128);   // full0
        mb_init(ubar + 8, 128);   // full1
        mb_init(ubar + 16, 4);    // empty0
        mb_init(ubar + 24, 4);    // empty1
    }

    auto load_kv = [&](int j, int buf) {
        const uint32_t uK = uPs + (8704 + buf * ABUF) * 4;
        const uint32_t uV = uPs + (17408 + buf * ABUF) * 4;
        #pragma unroll
        for (int i = 0; i < 8; i++) {
            int idx = tid + i * 128; int r = idx >> 4, cc = idx & 15;
            cpa(uK + (r * 68 + cc * 4) * 4, Kg + (size_t)(j * 64 + r) * DH + cc * 4);
            cpa(uV + (r * 68 + cc * 4) * 4, Vg + (size_t)r * TT + j * 64 + cc * 4);
        }
    };

    // prologue: stage Q into Ps, load first KV block (group wait + CTA barrier,
    // which also publishes the mbarrier inits)
    #pragma unroll
    for (int i = 0; i < 16; i++) {
        int idx = tid + i * 128; int r = idx >> 4, cc = idx & 15;
        cpa(uPs + (r * 68 + cc * 4) * 4, Qg + (size_t)r * DH + cc * 4);
    }
    load_kv(j0, 0);
    cp_commit();
    cp_wait<0>();
    __syncthreads();

    // Q fragments -> registers (warp-private rows)
    uint32_t A[2][8][4];
    #pragma unroll
    for (int tm = 0; tm < 2; tm++) {
        const int base = rb + tm * 16;
        #pragma unroll
        for (int ks = 0; ks < 8; ks++) {
            A[tm][ks][0] = Ps[(base + g) * 68 + ks * 8 + q];
            A[tm][ks][1] = Ps[(base + 8 + g) * 68 + ks * 8 + q];
            A[tm][ks][2] = Ps[(base + g) * 68 + ks * 8 + q + 4];
            A[tm][ks][3] = Ps[(base + 8 + g) * 68 + ks * 8 + q + 4];
        }
    }
    __syncwarp();   // Ps rows are warp-private from here on (P storage)

    float O[2][8][4];
    #pragma unroll
    for (int tm = 0; tm < 2; tm++)
        #pragma unroll
        for (int tn = 0; tn < 8; tn++)
            #pragma unroll
            for (int k = 0; k < 4; k++) O[tm][tn][k] = 0.f;
    float mv[4], lv[4];
    #pragma unroll
    for (int i = 0; i < 4; i++) { mv[i] = -1e30f; lv[i] = 0.f; }

    const int r0 = qb * 128 + rb + g;

    // per-warp parities: full start 0; empty0 starts 0, empty1 starts 1
    int pf0 = 0, pf1 = 0, pe0 = 0, pe1 = 1;

    for (int jj = 0; jj < nloc; jj++) {
        const int j = j0 + jj;
        const int b = jj & 1;
        if (jj) {
            if (b == 0) { mb_wait(ubar + 0, pf0); pf0 ^= 1; }
            else        { mb_wait(ubar + 8, pf1); pf1 ^= 1; }
        }
        if (jj + 1 < nloc) {
            const int nb = (jj + 1) & 1;
            if (nb == 0) { mb_wait(ubar + 16, pe0); pe0 ^= 1; }
            else         { mb_wait(ubar + 24, pe1); pe1 ^= 1; }
            load_kv(j + 1, nb);
            cp_mb_arrive_noinc(ubar + nb * 8);   // arm full[nb] (all 128 threads)
        }
        const uint32_t* Ks = sm + 8704 + b * ABUF;
        const uint32_t* Vs = sm + 17408 + b * ABUF;

        // S = Q @ K^T (log2 domain; Q pre-scaled)
        float S[2][8][4];
        #pragma unroll
        for (int tm = 0; tm < 2; tm++)
            #pragma unroll
            for (int tn = 0; tn < 8; tn++)
                #pragma unroll
                for (int k = 0; k < 4; k++) S[tm][tn][k] = 0.f;
        #pragma unroll
        for (int ks = 0; ks < 8; ks++) {
            #pragma unroll
            for (int tn = 0; tn < 8; tn++) {
                uint32_t bb[2];
                bb[0] = Ks[(tn * 8 + g) * 68 + ks * 8 + q];
                bb[1] = Ks[(tn * 8 + g) * 68 + ks * 8 + q + 4];
                mma8(S[0][tn], A[0][ks], bb);
                mma8(S[1][tn], A[1][ks], bb);
            }
        }

        // causal mask (diagonal key-blocks only; j is absolute)
        if (j >= 2 * qb) {
            const int kb = j * 64;
            #pragma unroll
            for (int tn = 0; tn < 8; tn++) {
                const int col = kb + tn * 8 + 2 * q;
                #pragma unroll
                for (int tm = 0; tm < 2; tm++) {
                    const int ra = r0 + tm * 16, rb2 = ra + 8;
                    if (col > ra)      S[tm][tn][0] = -1e30f;
                    if (col + 1 > ra)  S[tm][tn][1] = -1e30f;
                    if (col > rb2)     S[tm][tn][2] = -1e30f;
                    if (col + 1 > rb2) S[tm][tn][3] = -1e30f;
                }
            }
        }

        // online softmax over 4 rows
        float tmax[4] = { -1e30f, -1e30f, -1e30f, -1e30f };
        #pragma unroll
        for (int tm = 0; tm < 2; tm++)
            #pragma unroll
            for (int tn = 0; tn < 8; tn++) {
                tmax[tm * 2]     = fmaxf(tmax[tm * 2],     fmaxf(S[tm][tn][0], S[tm][tn][1]));
                tmax[tm * 2 + 1] = fmaxf(tmax[tm * 2 + 1], fmaxf(S[tm][tn][2], S[tm][tn][3]));
            }
        float al[4];
        #pragma unroll
        for (int i = 0; i < 4; i++) {
            tmax[i] = fmaxf(tmax[i], __shfl_xor_sync(0xffffffffu, tmax[i], 1));
            tmax[i] = fmaxf(tmax[i], __shfl_xor_sync(0xffffffffu, tmax[i], 2));
            const float mn = fmaxf(mv[i], tmax[i]);
            al[i] = ex2(mv[i] - mn);
            mv[i] = mn;
        }
        float rs[4] = { 0.f, 0.f, 0.f, 0.f };
        #pragma unroll
        for (int tm = 0; tm < 2; tm++)
            #pragma unroll
            for (int tn = 0; tn < 8; tn++) {
                S[tm][tn][0] = ex2(S[tm][tn][0] - mv[tm * 2]);
                S[tm][tn][1] = ex2(S[tm][tn][1] - mv[tm * 2]);
                S[tm][tn][2] = ex2(S[tm][tn][2] - mv[tm * 2 + 1]);
                S[tm][tn][3] = ex2(S[tm][tn][3] - mv[tm * 2 + 1]);
                rs[tm * 2]     += S[tm][tn][0] + S[tm][tn][1];
                rs[tm * 2 + 1] += S[tm][tn][2] + S[tm][tn][3];
            }
        #pragma unroll
        for (int i = 0; i < 4; i++) {
            rs[i] += __shfl_xor_sync(0xffffffffu, rs[i], 1);
            rs[i] += __shfl_xor_sync(0xffffffffu, rs[i], 2);
            lv[i] = lv[i] * al[i] + rs[i];
        }

        // P -> smem (warp-private rows)
        #pragma unroll
        for (int tm = 0; tm < 2; tm++) {
            const int base = rb + tm * 16;
            #pragma unroll
            for (int tn = 0; tn < 8; tn++) {
                uint2 p0 = { tf32r(S[tm][tn][0]), tf32r(S[tm][tn][1]) };
                uint2 p1 = { tf32r(S[tm][tn][2]), tf32r(S[tm][tn][3]) };
                *(uint2*)(Ps + (base + g) * 68 + tn * 8 + 2 * q) = p0;
                *(uint2*)(Ps + (base + 8 + g) * 68 + tn * 8 + 2 * q) = p1;
            }
        }
        __syncwarp();

        // rescale O, accumulate P @ V
        #pragma unroll
        for (int tm = 0; tm < 2; tm++)
            #pragma unroll
            for (int tn = 0; tn < 8; tn++) {
                O[tm][tn][0] *= al[tm * 2];     O[tm][tn][1] *= al[tm * 2];
                O[tm][tn][2] *= al[tm * 2 + 1]; O[tm][tn][3] *= al[tm * 2 + 1];
            }
        #pragma unroll
        for (int ks = 0; ks < 8; ks++) {
            uint32_t a[2][4];
            #pragma unroll
            for (int tm = 0; tm < 2; tm++) {
                const int base = rb + tm * 16;
                a[tm][0] = Ps[(base + g) * 68 + ks * 8 + q];
                a[tm][1] = Ps[(base + 8 + g) * 68 + ks * 8 + q];
                a[tm][2] = Ps[(base + g) * 68 + ks * 8 + q + 4];
                a[tm][3] = Ps[(base + 8 + g) * 68 + ks * 8 + q + 4];
            }
            #pragma unroll
            for (int tn = 0; tn < 8; tn++) {
                uint32_t bb[2];
                bb[0] = Vs[(tn * 8 + g) * 68 + ks * 8 + q];
                bb[1] = Vs[(tn * 8 + g) * 68 + ks * 8 + q + 4];
                mma8(O[0][tn], a[0], bb);
                mma8(O[1][tn], a[1], bb);
            }
        }
        __syncwarp();
        if (lane == 0) mb_arrive(ubar + 16 + b * 8);   // release stage b
    }

    if (!split) {
        // unsplit: normalize and write g_att (tf32-rounded for the out GEMM)
        #pragma unroll
        for (int tm = 0; tm < 2; tm++) {
            const int ra = r0 + tm * 16;
            const float i0 = 1.f / lv[tm * 2], i1 = 1.f / lv[tm * 2 + 1];
            #pragma unroll
            for (int tn = 0; tn < 8; tn++) {
                const int d = tn * 8 + 2 * q;
                uint2 v0 = { tf32r(O[tm][tn][0] * i0), tf32r(O[tm][tn][1] * i0) };
                uint2 v1 = { tf32r(O[tm][tn][2] * i1), tf32r(O[tm][tn][3] * i1) };
                *(uint2*)(g_att + (size_t)ra * CC + h * DH + d) = v0;
                *(uint2*)(g_att + (size_t)(ra + 8) * CC + h * DH + d) = v1;
            }
        }
    } else {
        // split: write unnormalized O + (m, l) to scratch (rows 0..3071 per head)
        const int sb = (qb - 8) * 128;
        float* poB = g_po + ((size_t)part * HH + h) * 3072 * 64;
        #pragma unroll
        for (int tm = 0; tm < 2; tm++) {
            const int lr = rb + tm * 16 + g;
            #pragma unroll
            for (int tn = 0; tn < 8; tn++) {
                const int d = tn * 8 + 2 * q;
                float2 v0 = { O[tm][tn][0], O[tm][tn][1] };
                float2 v1 = { O[tm][tn][2], O[tm][tn][3] };
                *(float2*)(poB + (size_t)(sb + lr) * 64 + d) = v0;
                *(float2*)(poB + (size_t)(sb + lr + 8) * 64 + d) = v1;
            }
            if (q == 0) {
                const size_t mi = ((size_t)part * HH + h) * 3072 + sb;
                g_pm[mi + lr]     = mv[tm * 2];     g_pl[mi + lr]     = lv[tm * 2];
                g_pm[mi + lr + 8] = mv[tm * 2 + 1]; g_pl[mi + lr + 8] = lv[tm * 2 + 1];
            }
        }
    }
}

// ---------------- merge split-K partials (token rows 1024..4095, 2-4 parts) ----------
__global__ __launch_bounds__(256) void merge_k()
{
    const int idx = blockIdx.x * 256 + threadIdx.x;   // 12 * 3072 * 16 = 589824
    const int d4  = (idx & 15) * 4;
    const int row = (idx >> 4) % 3072;
    const int h   = idx / (3072 * 16);

    const int qb = 8 + (row >> 7);
    const int np = (qb >= 24) ? 4 : (qb >= 16) ? 3 : 2;

    const size_t mi0 = (size_t)h * 3072 + row;
    float m = -1e30f;
    #pragma unroll
    for (int p = 0; p < 4; p++)
        if (p < np) m = fmaxf(m, g_pm[(size_t)p * HH * 3072 + mi0]);

    float den = 0.f;
    float4 acc = { 0.f, 0.f, 0.f, 0.f };
    #pragma unroll
    for (int p = 0; p < 4; p++) {
        if (p >= np) break;
        const size_t mi = (size_t)p * HH * 3072 + mi0;
        const float w = ex2(g_pm[mi] - m);
        den += g_pl[mi] * w;
        const float4 o = *(const float4*)(g_po + ((size_t)p * HH + h) * 3072 * 64
                                               + (size_t)row * 64 + d4);
        acc.x += o.x * w; acc.y += o.y * w; acc.z += o.z * w; acc.w += o.w * w;
    }
    const float inv = 1.f / den;
    uint4 r;
    r.x = tf32r(acc.x * inv); r.y = tf32r(acc.y * inv);
    r.z = tf32r(acc.z * inv); r.w = tf32r(acc.w * inv);

    const int tok = qb * 128 + (row & 127);
    *(uint4*)(g_att + (size_t)tok * CC + h * DH + d4) = r;
}

// ---------------- launcher ----------------
extern "C" void kernel_launch(void* const* d_in, const int* in_sizes, int n_in,
                              void* d_out, int out_size)
{
    const float* x  = (const float*)d_in[0];
    const float* wq = (const float*)d_in[1];
    const float* bq = (const float*)d_in[2];
    const float* wk = (const float*)d_in[3];
    const float* bk = (const float*)d_in[4];
    const float* wv = (const float*)d_in[5];
    const float* bv = (const float*)d_in[6];
    const float* wo = (const float*)d_in[7];
    const float* bo = (const float*)d_in[8];

    const int GSM = 3 * GBUFSZ * 4;    // 110592 B (3-stage)
    const int ASM = 26112 * 4;         // 104448 B
    cudaFuncSetAttribute(gemm_k<0>, cudaFuncAttributeMaxDynamicSharedMemorySize, GSM);
    cudaFuncSetAttribute(gemm_k<1>, cudaFuncAttributeMaxDynamicSharedMemorySize, GSM);
    cudaFuncSetAttribute(attn,      cudaFuncAttributeMaxDynamicSharedMemorySize, ASM);

    float* xt_dev;  cudaGetSymbolAddress((void**)&xt_dev,  g_xt);
    float* wt_dev;  cudaGetSymbolAddress((void**)&wt_dev,  g_wt);
    float* wot_dev; cudaGetSymbolAddress((void**)&wot_dev, g_wot);
    float* att_dev; cudaGetSymbolAddress((void**)&att_dev, g_att);

    prep<<<3648, 256>>>(x, wq, wk, wv, wo);
    gemm_k<0><<<dim3(32, 18), 256, GSM>>>(xt_dev, wt_dev, bq, bk, bv, nullptr);
    attn<<<dim3(80, 12), 128, ASM>>>();
    merge_k<<<2304, 256>>>();
    gemm_k<1><<<dim3(32, 6), 256, GSM>>>(att_dev, wot_dev, bo, nullptr, nullptr, (float*)d_out);
}